// round 11
// baseline (speedup 1.0000x reference)
#include <cuda_runtime.h>
#include <math.h>
#include <stdint.h>

// ---------------------------------------------------------------------------
// SSITrimLoss: masked scale/shift-invariant trimmed L1 loss.
// Pipeline (4 launches) — R10 inner loops, small launches merged away:
//   1. pack    : moments + compact valid (p,g) pairs; zero hist/counters/out
//   2. hist    : abk per block from partials; res bits -> 2048-bin count hist
//   3. compact : abk + level-0 selection scan per block (L2-hot); sweep 1:
//                below-bin sum + match count, ONE atomic reserve; sweep 2
//                (L1-hot) gathers in-bin candidates -> contiguous g_cand
//   4. finish  : 21-bit refine over contiguous candidates (ILP-4) ->
//                atomicAdd(out, loss/B)
// Selection is bit-exact (monotone uint encoding of non-negative floats).
// ---------------------------------------------------------------------------

#define BB    32
#define NMAX  491520
#define TPB   256
#define BLKX  32
#define SEGLEN (NMAX / BLKX)
#define FULLM 0xffffffffu

__device__ __align__(16) float2       g_pair[(size_t)BB * NMAX];
__device__ __align__(16) unsigned int g_cand[(size_t)BB * NMAX];
__device__ float              g_part[BB][BLKX][5];
__device__ int                g_segcnt[BB][BLKX];
__device__ unsigned int       g_hcnt[BB][2048];
__device__ int                g_k[BB];
__device__ long long          g_rank[BB];
__device__ int                g_sel0[BB];
__device__ double             g_sumbelow[BB];
__device__ long long          g_cntbelow[BB];
__device__ int                g_candcnt[BB];

// ------------------------- warp reduce/scan helpers ------------------------
__device__ __forceinline__ float warp_sum(float v) {
    #pragma unroll
    for (int off = 16; off; off >>= 1) v += __shfl_down_sync(FULLM, v, off);
    return v;
}
__device__ __forceinline__ double warp_sum_d(double v) {
    #pragma unroll
    for (int off = 16; off; off >>= 1) v += __shfl_down_sync(FULLM, v, off);
    return v;
}
__device__ __forceinline__ long long warp_sum_ll(long long v) {
    #pragma unroll
    for (int off = 16; off; off >>= 1) v += __shfl_down_sync(FULLM, v, off);
    return v;
}
__device__ __forceinline__ int warp_sum_i(int v) {
    #pragma unroll
    for (int off = 16; off; off >>= 1) v += __shfl_down_sync(FULLM, v, off);
    return v;
}
__device__ __forceinline__ int warp_scan_incl(int v, int lane) {
    #pragma unroll
    for (int off = 1; off < 32; off <<= 1) {
        int t = __shfl_up_sync(FULLM, v, off);
        if (lane >= off) v += t;
    }
    return v;
}

// alpha/beta/k from per-block partials; deterministic, identical in all blocks.
struct ABK { float a, be; int k; long long r; };
__device__ __forceinline__ void compute_abk(int b, int tid, ABK* s_out) {
    if (tid < 32) {
        double v0 = (double)g_part[b][tid][0];
        double v1 = (double)g_part[b][tid][1];
        double v2 = (double)g_part[b][tid][2];
        double v3 = (double)g_part[b][tid][3];
        double v4 = (double)g_part[b][tid][4];
        v0 = warp_sum_d(v0); v1 = warp_sum_d(v1); v2 = warp_sum_d(v2);
        v3 = warp_sum_d(v3); v4 = warp_sum_d(v4);
        if (tid == 0) {
            double n  = v0;
            double ns = n < 1.0 ? 1.0 : n;
            double md = v1 / ns, mz = v2 / ns;
            double var = v3 / ns - md * md;
            double cov = v4 / ns - md * mz;
            double alpha = cov / (var + 1e-6);
            s_out->a  = (float)alpha;
            s_out->be = (float)(mz - alpha * md);
            int k = (int)floorf(0.8f * (float)n);  // reference-matching f32 arith
            s_out->k = k;
            s_out->r = (long long)k - 1;
        }
    }
}

// ------------------------ 1. pack (moments + gather) -----------------------
__global__ __launch_bounds__(TPB) void pack_kernel(
        const float* __restrict__ pred, const float* __restrict__ gt,
        const int* __restrict__ mask, int N, float* __restrict__ out0) {
    int b = blockIdx.y;
    // zero this sample's hist slice (2048/32 = 64 entries per block)
    if (threadIdx.x < 64) g_hcnt[b][(blockIdx.x << 6) + threadIdx.x] = 0u;
    if (blockIdx.x == 0 && threadIdx.x == 0) {
        g_candcnt[b] = 0;
        g_sumbelow[b] = 0.0;
        if (b == 0) *out0 = 0.f;
    }

    int n4 = N >> 2;
    int chunk4 = n4 / BLKX;
    int start = blockIdx.x * chunk4;
    int end   = (blockIdx.x == BLKX - 1) ? n4 : start + chunk4;

    const float4* p4 = reinterpret_cast<const float4*>(pred) + (size_t)b * n4;
    const float4* g4 = reinterpret_cast<const float4*>(gt)   + (size_t)b * n4;
    const int4*   m4 = reinterpret_cast<const int4*>(mask)   + (size_t)b * n4;
    float2* out = g_pair + (size_t)b * NMAX + (size_t)blockIdx.x * SEGLEN;

    __shared__ int s_cnt;
    if (threadIdx.x == 0) s_cnt = 0;
    __syncthreads();

    int lane = threadIdx.x & 31;
    float sn = 0.f, sp = 0.f, sg = 0.f, spp = 0.f, spg = 0.f;

    for (int i = start + threadIdx.x; i < end; i += TPB) {
        float4 p = p4[i]; float4 g = g4[i]; int4 m = m4[i];
        bool v0 = m.x > 0, v1 = m.y > 0, v2 = m.z > 0, v3 = m.w > 0;
        if (v0) { sn += 1.f; sp += p.x; sg += g.x; spp += p.x*p.x; spg += p.x*g.x; }
        if (v1) { sn += 1.f; sp += p.y; sg += g.y; spp += p.y*p.y; spg += p.y*g.y; }
        if (v2) { sn += 1.f; sp += p.z; sg += g.z; spp += p.z*p.z; spg += p.z*g.z; }
        if (v3) { sn += 1.f; sp += p.w; sg += g.w; spp += p.w*p.w; spg += p.w*g.w; }
        int vc = (int)v0 + (int)v1 + (int)v2 + (int)v3;
        int incl = warp_scan_incl(vc, lane);
        int wtotal = __shfl_sync(FULLM, incl, 31);
        int base = 0;
        if (lane == 31 && wtotal) base = atomicAdd(&s_cnt, wtotal);
        base = __shfl_sync(FULLM, base, 31);
        int o = base + incl - vc;
        if (v0) out[o++] = make_float2(p.x, g.x);
        if (v1) out[o++] = make_float2(p.y, g.y);
        if (v2) out[o++] = make_float2(p.z, g.z);
        if (v3) out[o]   = make_float2(p.w, g.w);
    }

    sn = warp_sum(sn); sp = warp_sum(sp); sg = warp_sum(sg);
    spp = warp_sum(spp); spg = warp_sum(spg);
    __shared__ float ws[5][8];
    int w = threadIdx.x >> 5;
    if (lane == 0) { ws[0][w]=sn; ws[1][w]=sp; ws[2][w]=sg; ws[3][w]=spp; ws[4][w]=spg; }
    __syncthreads();
    if (w == 0) {
        float a0 = lane < 8 ? ws[0][lane] : 0.f;
        float a1 = lane < 8 ? ws[1][lane] : 0.f;
        float a2 = lane < 8 ? ws[2][lane] : 0.f;
        float a3 = lane < 8 ? ws[3][lane] : 0.f;
        float a4 = lane < 8 ? ws[4][lane] : 0.f;
        a0 = warp_sum(a0); a1 = warp_sum(a1); a2 = warp_sum(a2);
        a3 = warp_sum(a3); a4 = warp_sum(a4);
        if (lane == 0) {
            g_part[b][blockIdx.x][0] = a0;
            g_part[b][blockIdx.x][1] = a1;
            g_part[b][blockIdx.x][2] = a2;
            g_part[b][blockIdx.x][3] = a3;
            g_part[b][blockIdx.x][4] = a4;
            g_segcnt[b][blockIdx.x] = s_cnt;
        }
    }
}

// ------------------------------ 2. hist ------------------------------------
__global__ __launch_bounds__(TPB) void hist_kernel() {
    int b = blockIdx.y;
    __shared__ ABK s_abk;
    __shared__ unsigned int sh[2048];
    compute_abk(b, threadIdx.x, &s_abk);
    for (int i = threadIdx.x; i < 2048; i += TPB) sh[i] = 0u;
    __syncthreads();

    int cnt = g_segcnt[b][blockIdx.x];
    const float2* in = g_pair + (size_t)b * NMAX + (size_t)blockIdx.x * SEGLEN;
    float a = s_abk.a, be = s_abk.be;

    for (int i = threadIdx.x; i < cnt; i += TPB) {
        float2 pg = in[i];
        float r = fabsf(fmaf(a, pg.x, be) - pg.y);
        atomicAdd(&sh[__float_as_uint(r) >> 21], 1u);
    }
    __syncthreads();
    for (int i = threadIdx.x; i < 2048; i += TPB) {
        unsigned c = sh[i];
        if (c) atomicAdd(&g_hcnt[b][i], c);
    }
}

// ------------------------------ 3. compact ---------------------------------
__global__ __launch_bounds__(TPB) void compact_kernel() {
    int b = blockIdx.y;
    int tid = threadIdx.x;
    int lane = tid & 31, w = tid >> 5;

    __shared__ ABK s_abk;
    __shared__ int wtot[8];
    __shared__ int s_bin;
    __shared__ long long s_before, s_rankin;
    __shared__ int s_base, s_local;

    compute_abk(b, tid, &s_abk);
    if (tid == 0) { s_bin = -1; s_local = 0; }
    __syncthreads();
    long long r = s_abk.r;

    // level-0 selection scan over 2048 bins (identical in every block; L2-hot)
    unsigned int c[8];
    int mysum = 0;
    #pragma unroll
    for (int j = 0; j < 8; j++) { c[j] = g_hcnt[b][tid*8+j]; mysum += (int)c[j]; }
    int incl = warp_scan_incl(mysum, lane);
    if (lane == 31) wtot[w] = incl;
    __syncthreads();
    int wbase = 0;
    #pragma unroll
    for (int j = 0; j < 8; j++) wbase += (j < w) ? wtot[j] : 0;
    long long base = (long long)wbase + incl - mysum;
    if (r >= 0 && r >= base && r < base + mysum) {
        long long cum = base;
        #pragma unroll
        for (int j = 0; j < 8; j++) {
            if (r < cum + (long long)c[j]) {
                s_bin = tid*8+j; s_before = cum; s_rankin = r - cum; break;
            }
            cum += (long long)c[j];
        }
    }
    __syncthreads();

    int sel = s_bin;
    if (sel < 0) {                        // k == 0 case
        if (tid == 0 && blockIdx.x == 0) { g_sel0[b] = -1; g_k[b] = s_abk.k; }
        return;
    }
    unsigned selu = (unsigned)sel;

    int cnt = g_segcnt[b][blockIdx.x];
    const float2* in = g_pair + (size_t)b * NMAX + (size_t)blockIdx.x * SEGLEN;
    float a = s_abk.a, be = s_abk.be;

    // sweep 1: below-bin sum + match count
    float sbelow = 0.f;
    int   cmatch = 0;
    for (int i = tid; i < cnt; i += TPB) {
        float2 pg = in[i];
        float rr = fabsf(fmaf(a, pg.x, be) - pg.y);
        unsigned top = __float_as_uint(rr) >> 21;
        if (top < selu) sbelow += rr;
        else if (top == selu) cmatch++;
    }
    float sb = warp_sum(sbelow);
    int   cm = warp_sum_i(cmatch);
    __shared__ float wsum[8];
    __shared__ int   wcm[8];
    if (lane == 0) { wsum[w] = sb; wcm[w] = cm; }
    __syncthreads();
    if (w == 0) {
        float a0 = lane < 8 ? wsum[lane] : 0.f;
        int   c0 = lane < 8 ? wcm[lane] : 0;
        a0 = warp_sum(a0); c0 = warp_sum_i(c0);
        if (lane == 0) {
            s_base = (c0 > 0) ? atomicAdd(&g_candcnt[b], c0) : 0;
            if (a0 != 0.f) atomicAdd(&g_sumbelow[b], (double)a0);
            if (blockIdx.x == 0) {
                g_sel0[b] = sel;
                g_k[b] = s_abk.k;
                g_rank[b] = s_rankin;
                g_cntbelow[b] = s_before;   // exact from scan
            }
        }
    }
    __syncthreads();
    int cbase = s_base;
    unsigned int* cand = g_cand + (size_t)b * NMAX;

    // sweep 2 (segment is L1-hot from sweep 1): write matches contiguously
    for (int i = tid; i < cnt; i += TPB) {
        float2 pg = in[i];
        float rr = fabsf(fmaf(a, pg.x, be) - pg.y);
        unsigned bits = __float_as_uint(rr);
        if ((bits >> 21) == selu)
            cand[cbase + atomicAdd(&s_local, 1)] = bits;
    }
}

// ------------------------------ 4. finish ----------------------------------
#define FTPB 1024
__global__ __launch_bounds__(FTPB) void finish_kernel(float* __restrict__ out0) {
    int b = blockIdx.x;
    int tid = threadIdx.x;
    int lane = tid & 31, w = tid >> 5;
    int sel0 = g_sel0[b];
    int k = g_k[b];

    __shared__ unsigned int hist[2048];
    __shared__ int wtot[32];
    __shared__ int s_bin;
    __shared__ long long s_before;
    __shared__ double sred[32];
    __shared__ long long lred[32];

    if (sel0 < 0 || k <= 0) return;   // contributes 0 to the mean

    int m = g_candcnt[b];
    long long rw = g_rank[b];
    const unsigned int* cand = g_cand + (size_t)b * NMAX;

    // ---- pass A: bits[20:10], 2048 bins (4x unrolled loads for MLP) ----
    for (int i = tid; i < 2048; i += FTPB) hist[i] = 0u;
    __syncthreads();
    {
        int i = tid;
        for (; i + 3*FTPB < m; i += 4*FTPB) {
            unsigned b0 = cand[i];
            unsigned b1 = cand[i + FTPB];
            unsigned b2 = cand[i + 2*FTPB];
            unsigned b3 = cand[i + 3*FTPB];
            atomicAdd(&hist[(b0 >> 10) & 2047u], 1u);
            atomicAdd(&hist[(b1 >> 10) & 2047u], 1u);
            atomicAdd(&hist[(b2 >> 10) & 2047u], 1u);
            atomicAdd(&hist[(b3 >> 10) & 2047u], 1u);
        }
        for (; i < m; i += FTPB)
            atomicAdd(&hist[(cand[i] >> 10) & 2047u], 1u);
    }
    __syncthreads();
    {
        int c0 = (int)hist[tid*2], c1 = (int)hist[tid*2+1];
        int mysum = c0 + c1;
        int incl = warp_scan_incl(mysum, lane);
        if (lane == 31) wtot[w] = incl;
        __syncthreads();
        int wbase = 0;
        for (int j = 0; j < w; j++) wbase += wtot[j];
        long long base = (long long)wbase + incl - mysum;
        if (rw >= base && rw < base + mysum) {
            if (rw < base + c0) { s_bin = tid*2;   s_before = base; }
            else                { s_bin = tid*2+1; s_before = base + c0; }
        }
        __syncthreads();
    }
    int selA = s_bin;
    rw -= s_before;
    __syncthreads();

    // ---- pass B: bits[9:0], 1024 bins (4x unrolled) ----
    for (int i = tid; i < 1024; i += FTPB) hist[i] = 0u;
    __syncthreads();
    {
        unsigned selAu = (unsigned)selA;
        int i = tid;
        for (; i + 3*FTPB < m; i += 4*FTPB) {
            unsigned b0 = cand[i];
            unsigned b1 = cand[i + FTPB];
            unsigned b2 = cand[i + 2*FTPB];
            unsigned b3 = cand[i + 3*FTPB];
            if (((b0 >> 10) & 2047u) == selAu) atomicAdd(&hist[b0 & 1023u], 1u);
            if (((b1 >> 10) & 2047u) == selAu) atomicAdd(&hist[b1 & 1023u], 1u);
            if (((b2 >> 10) & 2047u) == selAu) atomicAdd(&hist[b2 & 1023u], 1u);
            if (((b3 >> 10) & 2047u) == selAu) atomicAdd(&hist[b3 & 1023u], 1u);
        }
        for (; i < m; i += FTPB) {
            unsigned bits = cand[i];
            if (((bits >> 10) & 2047u) == selAu)
                atomicAdd(&hist[bits & 1023u], 1u);
        }
    }
    __syncthreads();
    {
        int mysum = (int)hist[tid & 1023];
        int incl = warp_scan_incl(mysum, lane);
        if (lane == 31) wtot[w] = incl;
        __syncthreads();
        int wbase = 0;
        for (int j = 0; j < w; j++) wbase += wtot[j];
        long long base = (long long)wbase + incl - mysum;
        if (rw >= base && rw < base + mysum) s_bin = tid;
        __syncthreads();
    }
    int selB = s_bin;
    unsigned v_bits = ((unsigned)sel0 << 21) | ((unsigned)selA << 10) | (unsigned)selB;
    float v = __uint_as_float(v_bits);

    // ---- pass C: sum/count of candidates strictly below v (4x unrolled) ----
    double s = 0.0;
    long long c = 0;
    {
        int i = tid;
        for (; i + 3*FTPB < m; i += 4*FTPB) {
            unsigned b0 = cand[i];
            unsigned b1 = cand[i + FTPB];
            unsigned b2 = cand[i + 2*FTPB];
            unsigned b3 = cand[i + 3*FTPB];
            if (b0 < v_bits) { s += (double)__uint_as_float(b0); c++; }
            if (b1 < v_bits) { s += (double)__uint_as_float(b1); c++; }
            if (b2 < v_bits) { s += (double)__uint_as_float(b2); c++; }
            if (b3 < v_bits) { s += (double)__uint_as_float(b3); c++; }
        }
        for (; i < m; i += FTPB) {
            unsigned bits = cand[i];
            if (bits < v_bits) { s += (double)__uint_as_float(bits); c++; }
        }
    }
    s = warp_sum_d(s);
    c = warp_sum_ll(c);
    if (lane == 0) { sred[w] = s; lred[w] = c; }
    __syncthreads();
    if (w == 0) {
        double sv = sred[lane];
        long long cv = lred[lane];
        sv = warp_sum_d(sv);
        cv = warp_sum_ll(cv);
        if (lane == 0) {
            long long total_less = g_cntbelow[b] + cv;
            double kept = g_sumbelow[b] + sv +
                          (double)((long long)k - total_less) * (double)v;
            float loss = (float)(kept / (double)k);
            atomicAdd(out0, loss / (float)BB);
        }
    }
}

// ------------------------------ launch -------------------------------------
extern "C" void kernel_launch(void* const* d_in, const int* in_sizes, int n_in,
                              void* d_out, int out_size) {
    const float* pred = (const float*)d_in[0];
    const float* gt   = (const float*)d_in[1];
    const int*   mask = (const int*)d_in[2];
    float* out = (float*)d_out;

    int total = in_sizes[0];
    int N = total / BB;

    dim3 grid(BLKX, BB);

    pack_kernel<<<grid, TPB>>>(pred, gt, mask, N, out);
    hist_kernel<<<grid, TPB>>>();
    compact_kernel<<<grid, TPB>>>();
    finish_kernel<<<BB, FTPB>>>(out);
}

// round 12
// speedup vs baseline: 1.1666x; 1.1666x over previous
#include <cuda_runtime.h>
#include <math.h>
#include <stdint.h>

// ---------------------------------------------------------------------------
// SSITrimLoss: masked scale/shift-invariant trimmed L1 loss.
// Pipeline (7 launches) — R10 structure (measured best), pack inner loop
// switched from 5-shfl scan to 4 parallel ballots (shorter dependent chain):
//   1. pack      : moments + compact valid (p,g) pairs per block segment
//   2. finalize  : alpha/beta/k per sample; zero hists
//   3. hist      : res=|a*p+b-g| from pairs, 2048-bin count hist
//   4. select0   : pick level-0 bin + rank-within (hierarchical scan)
//   5. compact   : pairs again (L2-hot): below-bin sum/count + gather in-bin
//   6. finish    : per-sample 21-bit refine over candidates (4x unrolled MLP)
//   7. reduce    : mean over B -> out
// Selection is bit-exact (monotone uint encoding of non-negative floats).
// ---------------------------------------------------------------------------

#define BB    32
#define NMAX  491520
#define TPB   256
#define BLKX  32
#define SEGLEN (NMAX / BLKX)
#define FULLM 0xffffffffu

__device__ __align__(16) float2       g_pair[(size_t)BB * NMAX];
__device__ __align__(16) unsigned int g_cand[(size_t)BB * NMAX];
__device__ float              g_part[BB][BLKX][5];
__device__ int                g_segcnt[BB][BLKX];
__device__ unsigned int       g_hcnt[BB][2048];
__device__ float              g_alpha[BB], g_beta[BB];
__device__ int                g_k[BB];
__device__ long long          g_rank[BB];
__device__ int                g_sel0[BB];
__device__ double             g_sumbelow[BB];
__device__ unsigned long long g_cntbelow[BB];
__device__ int                g_candcnt[BB];
__device__ float              g_loss[BB];

// ------------------------- warp reduce/scan helpers ------------------------
__device__ __forceinline__ float warp_sum(float v) {
    #pragma unroll
    for (int off = 16; off; off >>= 1) v += __shfl_down_sync(FULLM, v, off);
    return v;
}
__device__ __forceinline__ double warp_sum_d(double v) {
    #pragma unroll
    for (int off = 16; off; off >>= 1) v += __shfl_down_sync(FULLM, v, off);
    return v;
}
__device__ __forceinline__ long long warp_sum_ll(long long v) {
    #pragma unroll
    for (int off = 16; off; off >>= 1) v += __shfl_down_sync(FULLM, v, off);
    return v;
}
__device__ __forceinline__ int warp_sum_i(int v) {
    #pragma unroll
    for (int off = 16; off; off >>= 1) v += __shfl_down_sync(FULLM, v, off);
    return v;
}
__device__ __forceinline__ int warp_scan_incl(int v, int lane) {
    #pragma unroll
    for (int off = 1; off < 32; off <<= 1) {
        int t = __shfl_up_sync(FULLM, v, off);
        if (lane >= off) v += t;
    }
    return v;
}

// ------------------------ 1. pack (moments + gather) -----------------------
__global__ __launch_bounds__(TPB) void pack_kernel(
        const float* __restrict__ pred, const float* __restrict__ gt,
        const int* __restrict__ mask, int N) {
    int b = blockIdx.y;
    int n4 = N >> 2;
    int chunk4 = n4 / BLKX;
    int start = blockIdx.x * chunk4;
    int end   = (blockIdx.x == BLKX - 1) ? n4 : start + chunk4;

    const float4* p4 = reinterpret_cast<const float4*>(pred) + (size_t)b * n4;
    const float4* g4 = reinterpret_cast<const float4*>(gt)   + (size_t)b * n4;
    const int4*   m4 = reinterpret_cast<const int4*>(mask)   + (size_t)b * n4;
    float2* out = g_pair + (size_t)b * NMAX + (size_t)blockIdx.x * SEGLEN;

    __shared__ int s_cnt;
    if (threadIdx.x == 0) s_cnt = 0;
    __syncthreads();

    int lane = threadIdx.x & 31;
    unsigned lmask = (1u << lane) - 1u;
    float sn = 0.f, sp = 0.f, sg = 0.f, spp = 0.f, spg = 0.f;

    for (int i = start + threadIdx.x; i < end; i += TPB) {
        float4 p = p4[i]; float4 g = g4[i]; int4 m = m4[i];
        bool v0 = m.x > 0, v1 = m.y > 0, v2 = m.z > 0, v3 = m.w > 0;
        if (v0) { sn += 1.f; sp += p.x; sg += g.x; spp += p.x*p.x; spg += p.x*g.x; }
        if (v1) { sn += 1.f; sp += p.y; sg += g.y; spp += p.y*p.y; spg += p.y*g.y; }
        if (v2) { sn += 1.f; sp += p.z; sg += g.z; spp += p.z*p.z; spg += p.z*g.z; }
        if (v3) { sn += 1.f; sp += p.w; sg += g.w; spp += p.w*p.w; spg += p.w*g.w; }
        // 4 independent ballots (short dependent chain), one shared atomic.
        unsigned bal0 = __ballot_sync(FULLM, v0);
        unsigned bal1 = __ballot_sync(FULLM, v1);
        unsigned bal2 = __ballot_sync(FULLM, v2);
        unsigned bal3 = __ballot_sync(FULLM, v3);
        int c0   = __popc(bal0);
        int c01  = c0  + __popc(bal1);
        int c012 = c01 + __popc(bal2);
        int tot  = c012 + __popc(bal3);
        int base = 0;
        if (lane == 0 && tot) base = atomicAdd(&s_cnt, tot);
        base = __shfl_sync(FULLM, base, 0);
        if (v0) out[base        + __popc(bal0 & lmask)] = make_float2(p.x, g.x);
        if (v1) out[base + c0   + __popc(bal1 & lmask)] = make_float2(p.y, g.y);
        if (v2) out[base + c01  + __popc(bal2 & lmask)] = make_float2(p.z, g.z);
        if (v3) out[base + c012 + __popc(bal3 & lmask)] = make_float2(p.w, g.w);
    }

    sn = warp_sum(sn); sp = warp_sum(sp); sg = warp_sum(sg);
    spp = warp_sum(spp); spg = warp_sum(spg);
    __shared__ float ws[5][8];
    int w = threadIdx.x >> 5;
    if (lane == 0) { ws[0][w]=sn; ws[1][w]=sp; ws[2][w]=sg; ws[3][w]=spp; ws[4][w]=spg; }
    __syncthreads();
    if (w == 0) {
        float a0 = lane < 8 ? ws[0][lane] : 0.f;
        float a1 = lane < 8 ? ws[1][lane] : 0.f;
        float a2 = lane < 8 ? ws[2][lane] : 0.f;
        float a3 = lane < 8 ? ws[3][lane] : 0.f;
        float a4 = lane < 8 ? ws[4][lane] : 0.f;
        a0 = warp_sum(a0); a1 = warp_sum(a1); a2 = warp_sum(a2);
        a3 = warp_sum(a3); a4 = warp_sum(a4);
        if (lane == 0) {
            g_part[b][blockIdx.x][0] = a0;
            g_part[b][blockIdx.x][1] = a1;
            g_part[b][blockIdx.x][2] = a2;
            g_part[b][blockIdx.x][3] = a3;
            g_part[b][blockIdx.x][4] = a4;
            g_segcnt[b][blockIdx.x] = s_cnt;
        }
    }
}

// ------------------------------ 2. finalize --------------------------------
__global__ void finalize_kernel() {
    int b = blockIdx.x;
    int tid = threadIdx.x;
    for (int i = tid; i < 2048; i += blockDim.x) g_hcnt[b][i] = 0u;
    if (tid == 0) {
        g_candcnt[b] = 0;
        g_sumbelow[b] = 0.0;
        g_cntbelow[b] = 0ull;
    }
    if (tid < 32) {
        double v0 = (double)g_part[b][tid][0];
        double v1 = (double)g_part[b][tid][1];
        double v2 = (double)g_part[b][tid][2];
        double v3 = (double)g_part[b][tid][3];
        double v4 = (double)g_part[b][tid][4];
        v0 = warp_sum_d(v0); v1 = warp_sum_d(v1); v2 = warp_sum_d(v2);
        v3 = warp_sum_d(v3); v4 = warp_sum_d(v4);
        if (tid == 0) {
            double n  = v0;
            double ns = n < 1.0 ? 1.0 : n;
            double md = v1 / ns, mz = v2 / ns;
            double var = v3 / ns - md * md;
            double cov = v4 / ns - md * mz;
            double alpha = cov / (var + 1e-6);
            double beta  = mz - alpha * md;
            g_alpha[b] = (float)alpha;
            g_beta[b]  = (float)beta;
            int k = (int)floorf(0.8f * (float)n);   // reference-matching f32 arith
            g_k[b] = k;
            g_rank[b] = (long long)k - 1;
        }
    }
}

// ------------------------------ 3. hist ------------------------------------
__global__ __launch_bounds__(TPB) void hist_kernel(int N) {
    int b = blockIdx.y;
    __shared__ unsigned int sh[2048];
    for (int i = threadIdx.x; i < 2048; i += TPB) sh[i] = 0u;
    __syncthreads();

    int cnt = g_segcnt[b][blockIdx.x];
    const float2* in = g_pair + (size_t)b * NMAX + (size_t)blockIdx.x * SEGLEN;
    float a = g_alpha[b], be = g_beta[b];

    for (int i = threadIdx.x; i < cnt; i += TPB) {
        float2 pg = in[i];
        float r = fabsf(fmaf(a, pg.x, be) - pg.y);
        atomicAdd(&sh[__float_as_uint(r) >> 21], 1u);
    }
    __syncthreads();
    for (int i = threadIdx.x; i < 2048; i += TPB) {
        unsigned c = sh[i];
        if (c) atomicAdd(&g_hcnt[b][i], c);
    }
}

// ------------------------------ 4. select0 ---------------------------------
__global__ void select0_kernel() {
    int b = blockIdx.x;
    int tid = threadIdx.x;
    int lane = tid & 31, w = tid >> 5;
    long long r = g_rank[b];

    __shared__ int wtot[8];
    __shared__ int s_bin;
    __shared__ long long s_before;
    if (tid == 0) s_bin = -1;

    unsigned int c[8];
    int mysum = 0;
    #pragma unroll
    for (int j = 0; j < 8; j++) { c[j] = g_hcnt[b][tid*8+j]; mysum += (int)c[j]; }
    int incl = warp_scan_incl(mysum, lane);
    if (lane == 31) wtot[w] = incl;
    __syncthreads();
    int wbase = 0;
    #pragma unroll
    for (int j = 0; j < 8; j++) wbase += (j < w) ? wtot[j] : 0;
    long long base = (long long)wbase + incl - mysum;

    if (r >= base && r < base + mysum) {
        long long cum = base;
        #pragma unroll
        for (int j = 0; j < 8; j++) {
            if (r < cum + (long long)c[j]) { s_bin = tid*8+j; s_before = cum; break; }
            cum += (long long)c[j];
        }
    }
    __syncthreads();
    if (tid == 0) {
        if (s_bin >= 0) {
            g_sel0[b] = s_bin;
            g_rank[b] = r - s_before;
        } else {
            g_sel0[b] = -1;    // k == 0 case
        }
    }
}

// ------------------------------ 5. compact ---------------------------------
__global__ __launch_bounds__(TPB) void compact_kernel(int N) {
    int b = blockIdx.y;
    int cnt = g_segcnt[b][blockIdx.x];
    const float2* in = g_pair + (size_t)b * NMAX + (size_t)blockIdx.x * SEGLEN;
    unsigned int* cand = g_cand + (size_t)b * NMAX;
    float a = g_alpha[b], be = g_beta[b];
    unsigned selu = (unsigned)g_sel0[b];      // -1 -> huge, never matches

    float sbelow = 0.f;
    int   cbelow = 0, cmatch = 0;

    // pass 1: counts + below-bin sums
    for (int i = threadIdx.x; i < cnt; i += TPB) {
        float2 pg = in[i];
        float r = fabsf(fmaf(a, pg.x, be) - pg.y);
        unsigned top = __float_as_uint(r) >> 21;
        if (top < selu) { sbelow += r; cbelow++; }
        else if (top == selu) cmatch++;
    }

    __shared__ float wsum[8];
    __shared__ int   wcb[8], wcm[8];
    __shared__ int   s_base, s_local;
    int lane = threadIdx.x & 31, w = threadIdx.x >> 5;
    float sb = warp_sum(sbelow);
    int   cb = warp_sum_i(cbelow);
    int   cm = warp_sum_i(cmatch);
    if (lane == 0) { wsum[w] = sb; wcb[w] = cb; wcm[w] = cm; }
    __syncthreads();
    if (w == 0) {
        float a0 = lane < 8 ? wsum[lane] : 0.f;
        int   b0 = lane < 8 ? wcb[lane] : 0;
        int   c0 = lane < 8 ? wcm[lane] : 0;
        a0 = warp_sum(a0); b0 = warp_sum_i(b0); c0 = warp_sum_i(c0);
        if (lane == 0) {
            s_local = 0;
            s_base = (c0 > 0) ? atomicAdd(&g_candcnt[b], c0) : 0;
            if (b0 > 0) {
                atomicAdd(&g_sumbelow[b], (double)a0);
                atomicAdd(&g_cntbelow[b], (unsigned long long)b0);
            }
        }
    }
    __syncthreads();
    int base = s_base;

    // pass 2: gather in-bin candidates (segment is L1-hot from pass 1)
    for (int i = threadIdx.x; i < cnt; i += TPB) {
        float2 pg = in[i];
        float r = fabsf(fmaf(a, pg.x, be) - pg.y);
        unsigned bits = __float_as_uint(r);
        if ((bits >> 21) == selu) {
            int p = atomicAdd(&s_local, 1);
            cand[base + p] = bits;
        }
    }
}

// ------------------------------ 6. finish ----------------------------------
#define FTPB 1024
__global__ __launch_bounds__(FTPB) void finish_kernel() {
    int b = blockIdx.x;
    int tid = threadIdx.x;
    int lane = tid & 31, w = tid >> 5;
    int k = g_k[b];

    __shared__ unsigned int hist[2048];
    __shared__ int wtot[32];
    __shared__ int s_bin;
    __shared__ long long s_before;
    __shared__ double sred[32];
    __shared__ long long lred[32];

    if (k <= 0) { if (tid == 0) g_loss[b] = 0.f; return; }

    int m = g_candcnt[b];
    long long rw = g_rank[b];
    int sel0 = g_sel0[b];
    const unsigned int* cand = g_cand + (size_t)b * NMAX;

    // ---- pass A: bits[20:10], 2048 bins (4x unrolled loads for MLP) ----
    for (int i = tid; i < 2048; i += FTPB) hist[i] = 0u;
    __syncthreads();
    {
        int i = tid;
        for (; i + 3*FTPB < m; i += 4*FTPB) {
            unsigned b0 = cand[i];
            unsigned b1 = cand[i + FTPB];
            unsigned b2 = cand[i + 2*FTPB];
            unsigned b3 = cand[i + 3*FTPB];
            atomicAdd(&hist[(b0 >> 10) & 2047u], 1u);
            atomicAdd(&hist[(b1 >> 10) & 2047u], 1u);
            atomicAdd(&hist[(b2 >> 10) & 2047u], 1u);
            atomicAdd(&hist[(b3 >> 10) & 2047u], 1u);
        }
        for (; i < m; i += FTPB)
            atomicAdd(&hist[(cand[i] >> 10) & 2047u], 1u);
    }
    __syncthreads();
    {
        int c0 = (int)hist[tid*2], c1 = (int)hist[tid*2+1];
        int mysum = c0 + c1;
        int incl = warp_scan_incl(mysum, lane);
        if (lane == 31) wtot[w] = incl;
        __syncthreads();
        int wbase = 0;
        for (int j = 0; j < w; j++) wbase += wtot[j];
        long long base = (long long)wbase + incl - mysum;
        if (rw >= base && rw < base + mysum) {
            if (rw < base + c0) { s_bin = tid*2;   s_before = base; }
            else                { s_bin = tid*2+1; s_before = base + c0; }
        }
        __syncthreads();
    }
    int selA = s_bin;
    rw -= s_before;
    __syncthreads();

    // ---- pass B: bits[9:0], 1024 bins (4x unrolled) ----
    for (int i = tid; i < 1024; i += FTPB) hist[i] = 0u;
    __syncthreads();
    {
        unsigned selAu = (unsigned)selA;
        int i = tid;
        for (; i + 3*FTPB < m; i += 4*FTPB) {
            unsigned b0 = cand[i];
            unsigned b1 = cand[i + FTPB];
            unsigned b2 = cand[i + 2*FTPB];
            unsigned b3 = cand[i + 3*FTPB];
            if (((b0 >> 10) & 2047u) == selAu) atomicAdd(&hist[b0 & 1023u], 1u);
            if (((b1 >> 10) & 2047u) == selAu) atomicAdd(&hist[b1 & 1023u], 1u);
            if (((b2 >> 10) & 2047u) == selAu) atomicAdd(&hist[b2 & 1023u], 1u);
            if (((b3 >> 10) & 2047u) == selAu) atomicAdd(&hist[b3 & 1023u], 1u);
        }
        for (; i < m; i += FTPB) {
            unsigned bits = cand[i];
            if (((bits >> 10) & 2047u) == selAu)
                atomicAdd(&hist[bits & 1023u], 1u);
        }
    }
    __syncthreads();
    {
        int mysum = (int)hist[tid & 1023];
        int incl = warp_scan_incl(mysum, lane);
        if (lane == 31) wtot[w] = incl;
        __syncthreads();
        int wbase = 0;
        for (int j = 0; j < w; j++) wbase += wtot[j];
        long long base = (long long)wbase + incl - mysum;
        if (rw >= base && rw < base + mysum) s_bin = tid;
        __syncthreads();
    }
    int selB = s_bin;
    unsigned v_bits = ((unsigned)sel0 << 21) | ((unsigned)selA << 10) | (unsigned)selB;
    float v = __uint_as_float(v_bits);

    // ---- pass C: sum/count of candidates strictly below v (4x unrolled) ----
    double s = 0.0;
    long long c = 0;
    {
        int i = tid;
        for (; i + 3*FTPB < m; i += 4*FTPB) {
            unsigned b0 = cand[i];
            unsigned b1 = cand[i + FTPB];
            unsigned b2 = cand[i + 2*FTPB];
            unsigned b3 = cand[i + 3*FTPB];
            if (b0 < v_bits) { s += (double)__uint_as_float(b0); c++; }
            if (b1 < v_bits) { s += (double)__uint_as_float(b1); c++; }
            if (b2 < v_bits) { s += (double)__uint_as_float(b2); c++; }
            if (b3 < v_bits) { s += (double)__uint_as_float(b3); c++; }
        }
        for (; i < m; i += FTPB) {
            unsigned bits = cand[i];
            if (bits < v_bits) { s += (double)__uint_as_float(bits); c++; }
        }
    }
    s = warp_sum_d(s);
    c = warp_sum_ll(c);
    if (lane == 0) { sred[w] = s; lred[w] = c; }
    __syncthreads();
    if (w == 0) {
        double sv = sred[lane];
        long long cv = lred[lane];
        sv = warp_sum_d(sv);
        cv = warp_sum_ll(cv);
        if (lane == 0) {
            long long total_less = (long long)g_cntbelow[b] + cv;
            double kept = g_sumbelow[b] + sv +
                          (double)((long long)k - total_less) * (double)v;
            g_loss[b] = (float)(kept / (double)k);
        }
    }
}

// ------------------------------ 7. reduce ----------------------------------
__global__ void reduce_kernel(float* out) {
    int b = threadIdx.x;
    float loss = (b < BB) ? g_loss[b] : 0.f;
    #pragma unroll
    for (int off = 16; off; off >>= 1) loss += __shfl_down_sync(FULLM, loss, off);
    if (b == 0) out[0] = loss / (float)BB;
}

// ------------------------------ launch -------------------------------------
extern "C" void kernel_launch(void* const* d_in, const int* in_sizes, int n_in,
                              void* d_out, int out_size) {
    const float* pred = (const float*)d_in[0];
    const float* gt   = (const float*)d_in[1];
    const int*   mask = (const int*)d_in[2];
    float* out = (float*)d_out;

    int total = in_sizes[0];
    int N = total / BB;

    dim3 grid(BLKX, BB);

    pack_kernel<<<grid, TPB>>>(pred, gt, mask, N);
    finalize_kernel<<<BB, TPB>>>();
    hist_kernel<<<grid, TPB>>>(N);
    select0_kernel<<<BB, TPB>>>();
    compact_kernel<<<grid, TPB>>>(N);
    finish_kernel<<<BB, FTPB>>>();
    reduce_kernel<<<1, 32>>>(out);
}

// round 13
// speedup vs baseline: 1.2150x; 1.0415x over previous
#include <cuda_runtime.h>
#include <math.h>
#include <stdint.h>

// ---------------------------------------------------------------------------
// SSITrimLoss: masked scale/shift-invariant trimmed L1 loss.
// Pipeline (5 launches) — R12 inner loops; select0 merged into compact,
// reduce merged into finish. finalize (abk + zeroing) kept as-is.
//   1. pack      : moments + compact valid (p,g) pairs per block segment
//   2. finalize  : alpha/beta/k per sample; zero hists/counters/out
//   3. hist      : res=|a*p+b-g| from pairs, 2048-bin count hist
//   4. compact   : per-block level-0 scan (L2-hot) + two sweeps of pairs ->
//                  below-bin sum + contiguous in-bin candidates
//   5. finish    : 21-bit refine (ILP-4) -> atomicAdd(out, loss/B)
// Selection is bit-exact (monotone uint encoding of non-negative floats).
// ---------------------------------------------------------------------------

#define BB    32
#define NMAX  491520
#define TPB   256
#define BLKX  32
#define SEGLEN (NMAX / BLKX)
#define FULLM 0xffffffffu

__device__ __align__(16) float2       g_pair[(size_t)BB * NMAX];
__device__ __align__(16) unsigned int g_cand[(size_t)BB * NMAX];
__device__ float              g_part[BB][BLKX][5];
__device__ int                g_segcnt[BB][BLKX];
__device__ unsigned int       g_hcnt[BB][2048];
__device__ float              g_alpha[BB], g_beta[BB];
__device__ int                g_k[BB];
__device__ long long          g_rank[BB];     // k-1 (set by finalize)
__device__ long long          g_rank2[BB];    // rank within selected bin
__device__ int                g_sel0[BB];
__device__ double             g_sumbelow[BB];
__device__ long long          g_cntbelow[BB];
__device__ int                g_candcnt[BB];

// ------------------------- warp reduce/scan helpers ------------------------
__device__ __forceinline__ float warp_sum(float v) {
    #pragma unroll
    for (int off = 16; off; off >>= 1) v += __shfl_down_sync(FULLM, v, off);
    return v;
}
__device__ __forceinline__ double warp_sum_d(double v) {
    #pragma unroll
    for (int off = 16; off; off >>= 1) v += __shfl_down_sync(FULLM, v, off);
    return v;
}
__device__ __forceinline__ long long warp_sum_ll(long long v) {
    #pragma unroll
    for (int off = 16; off; off >>= 1) v += __shfl_down_sync(FULLM, v, off);
    return v;
}
__device__ __forceinline__ int warp_sum_i(int v) {
    #pragma unroll
    for (int off = 16; off; off >>= 1) v += __shfl_down_sync(FULLM, v, off);
    return v;
}
__device__ __forceinline__ int warp_scan_incl(int v, int lane) {
    #pragma unroll
    for (int off = 1; off < 32; off <<= 1) {
        int t = __shfl_up_sync(FULLM, v, off);
        if (lane >= off) v += t;
    }
    return v;
}

// ------------------------ 1. pack (moments + gather) -----------------------
__global__ __launch_bounds__(TPB) void pack_kernel(
        const float* __restrict__ pred, const float* __restrict__ gt,
        const int* __restrict__ mask, int N) {
    int b = blockIdx.y;
    int n4 = N >> 2;
    int chunk4 = n4 / BLKX;
    int start = blockIdx.x * chunk4;
    int end   = (blockIdx.x == BLKX - 1) ? n4 : start + chunk4;

    const float4* p4 = reinterpret_cast<const float4*>(pred) + (size_t)b * n4;
    const float4* g4 = reinterpret_cast<const float4*>(gt)   + (size_t)b * n4;
    const int4*   m4 = reinterpret_cast<const int4*>(mask)   + (size_t)b * n4;
    float2* out = g_pair + (size_t)b * NMAX + (size_t)blockIdx.x * SEGLEN;

    __shared__ int s_cnt;
    if (threadIdx.x == 0) s_cnt = 0;
    __syncthreads();

    int lane = threadIdx.x & 31;
    unsigned lmask = (1u << lane) - 1u;
    float sn = 0.f, sp = 0.f, sg = 0.f, spp = 0.f, spg = 0.f;

    for (int i = start + threadIdx.x; i < end; i += TPB) {
        float4 p = p4[i]; float4 g = g4[i]; int4 m = m4[i];
        bool v0 = m.x > 0, v1 = m.y > 0, v2 = m.z > 0, v3 = m.w > 0;
        if (v0) { sn += 1.f; sp += p.x; sg += g.x; spp += p.x*p.x; spg += p.x*g.x; }
        if (v1) { sn += 1.f; sp += p.y; sg += g.y; spp += p.y*p.y; spg += p.y*g.y; }
        if (v2) { sn += 1.f; sp += p.z; sg += g.z; spp += p.z*p.z; spg += p.z*g.z; }
        if (v3) { sn += 1.f; sp += p.w; sg += g.w; spp += p.w*p.w; spg += p.w*g.w; }
        unsigned bal0 = __ballot_sync(FULLM, v0);
        unsigned bal1 = __ballot_sync(FULLM, v1);
        unsigned bal2 = __ballot_sync(FULLM, v2);
        unsigned bal3 = __ballot_sync(FULLM, v3);
        int c0   = __popc(bal0);
        int c01  = c0  + __popc(bal1);
        int c012 = c01 + __popc(bal2);
        int tot  = c012 + __popc(bal3);
        int base = 0;
        if (lane == 0 && tot) base = atomicAdd(&s_cnt, tot);
        base = __shfl_sync(FULLM, base, 0);
        if (v0) out[base        + __popc(bal0 & lmask)] = make_float2(p.x, g.x);
        if (v1) out[base + c0   + __popc(bal1 & lmask)] = make_float2(p.y, g.y);
        if (v2) out[base + c01  + __popc(bal2 & lmask)] = make_float2(p.z, g.z);
        if (v3) out[base + c012 + __popc(bal3 & lmask)] = make_float2(p.w, g.w);
    }

    sn = warp_sum(sn); sp = warp_sum(sp); sg = warp_sum(sg);
    spp = warp_sum(spp); spg = warp_sum(spg);
    __shared__ float ws[5][8];
    int w = threadIdx.x >> 5;
    if (lane == 0) { ws[0][w]=sn; ws[1][w]=sp; ws[2][w]=sg; ws[3][w]=spp; ws[4][w]=spg; }
    __syncthreads();
    if (w == 0) {
        float a0 = lane < 8 ? ws[0][lane] : 0.f;
        float a1 = lane < 8 ? ws[1][lane] : 0.f;
        float a2 = lane < 8 ? ws[2][lane] : 0.f;
        float a3 = lane < 8 ? ws[3][lane] : 0.f;
        float a4 = lane < 8 ? ws[4][lane] : 0.f;
        a0 = warp_sum(a0); a1 = warp_sum(a1); a2 = warp_sum(a2);
        a3 = warp_sum(a3); a4 = warp_sum(a4);
        if (lane == 0) {
            g_part[b][blockIdx.x][0] = a0;
            g_part[b][blockIdx.x][1] = a1;
            g_part[b][blockIdx.x][2] = a2;
            g_part[b][blockIdx.x][3] = a3;
            g_part[b][blockIdx.x][4] = a4;
            g_segcnt[b][blockIdx.x] = s_cnt;
        }
    }
}

// ------------------------------ 2. finalize --------------------------------
__global__ void finalize_kernel(float* __restrict__ out0) {
    int b = blockIdx.x;
    int tid = threadIdx.x;
    for (int i = tid; i < 2048; i += blockDim.x) g_hcnt[b][i] = 0u;
    if (tid == 0) {
        g_candcnt[b] = 0;
        g_sumbelow[b] = 0.0;
        if (b == 0) *out0 = 0.f;
    }
    if (tid < 32) {
        double v0 = (double)g_part[b][tid][0];
        double v1 = (double)g_part[b][tid][1];
        double v2 = (double)g_part[b][tid][2];
        double v3 = (double)g_part[b][tid][3];
        double v4 = (double)g_part[b][tid][4];
        v0 = warp_sum_d(v0); v1 = warp_sum_d(v1); v2 = warp_sum_d(v2);
        v3 = warp_sum_d(v3); v4 = warp_sum_d(v4);
        if (tid == 0) {
            double n  = v0;
            double ns = n < 1.0 ? 1.0 : n;
            double md = v1 / ns, mz = v2 / ns;
            double var = v3 / ns - md * md;
            double cov = v4 / ns - md * mz;
            double alpha = cov / (var + 1e-6);
            double beta  = mz - alpha * md;
            g_alpha[b] = (float)alpha;
            g_beta[b]  = (float)beta;
            int k = (int)floorf(0.8f * (float)n);   // reference-matching f32 arith
            g_k[b] = k;
            g_rank[b] = (long long)k - 1;
        }
    }
}

// ------------------------------ 3. hist ------------------------------------
__global__ __launch_bounds__(TPB) void hist_kernel() {
    int b = blockIdx.y;
    __shared__ unsigned int sh[2048];
    for (int i = threadIdx.x; i < 2048; i += TPB) sh[i] = 0u;
    __syncthreads();

    int cnt = g_segcnt[b][blockIdx.x];
    const float2* in = g_pair + (size_t)b * NMAX + (size_t)blockIdx.x * SEGLEN;
    float a = g_alpha[b], be = g_beta[b];

    for (int i = threadIdx.x; i < cnt; i += TPB) {
        float2 pg = in[i];
        float r = fabsf(fmaf(a, pg.x, be) - pg.y);
        atomicAdd(&sh[__float_as_uint(r) >> 21], 1u);
    }
    __syncthreads();
    for (int i = threadIdx.x; i < 2048; i += TPB) {
        unsigned c = sh[i];
        if (c) atomicAdd(&g_hcnt[b][i], c);
    }
}

// ---------------------- 4. compact (+level-0 select) -----------------------
__global__ __launch_bounds__(TPB) void compact_kernel() {
    int b = blockIdx.y;
    int tid = threadIdx.x;
    int lane = tid & 31, w = tid >> 5;

    __shared__ int wtot[8];
    __shared__ int s_bin;
    __shared__ long long s_before, s_rankin;
    __shared__ int s_base, s_local;

    if (tid == 0) { s_bin = -1; s_local = 0; }
    long long r = g_rank[b];      // k-1; finalize-owned, never overwritten
    __syncthreads();

    // level-0 selection scan over 2048 bins (identical in every block; L2-hot)
    unsigned int c[8];
    int mysum = 0;
    #pragma unroll
    for (int j = 0; j < 8; j++) { c[j] = g_hcnt[b][tid*8+j]; mysum += (int)c[j]; }
    int incl = warp_scan_incl(mysum, lane);
    if (lane == 31) wtot[w] = incl;
    __syncthreads();
    int wbase = 0;
    #pragma unroll
    for (int j = 0; j < 8; j++) wbase += (j < w) ? wtot[j] : 0;
    long long base = (long long)wbase + incl - mysum;
    if (r >= 0 && r >= base && r < base + mysum) {
        long long cum = base;
        #pragma unroll
        for (int j = 0; j < 8; j++) {
            if (r < cum + (long long)c[j]) {
                s_bin = tid*8+j; s_before = cum; s_rankin = r - cum; break;
            }
            cum += (long long)c[j];
        }
    }
    __syncthreads();

    int sel = s_bin;
    if (sel < 0) {                        // k == 0 case
        if (tid == 0 && blockIdx.x == 0) g_sel0[b] = -1;
        return;
    }
    unsigned selu = (unsigned)sel;

    int cnt = g_segcnt[b][blockIdx.x];
    const float2* in = g_pair + (size_t)b * NMAX + (size_t)blockIdx.x * SEGLEN;
    float a = g_alpha[b], be = g_beta[b];

    // sweep 1: below-bin sum + match count
    float sbelow = 0.f;
    int   cmatch = 0;
    for (int i = tid; i < cnt; i += TPB) {
        float2 pg = in[i];
        float rr = fabsf(fmaf(a, pg.x, be) - pg.y);
        unsigned top = __float_as_uint(rr) >> 21;
        if (top < selu) sbelow += rr;
        else if (top == selu) cmatch++;
    }
    float sb = warp_sum(sbelow);
    int   cm = warp_sum_i(cmatch);
    __shared__ float wsum[8];
    __shared__ int   wcm[8];
    if (lane == 0) { wsum[w] = sb; wcm[w] = cm; }
    __syncthreads();
    if (w == 0) {
        float a0 = lane < 8 ? wsum[lane] : 0.f;
        int   c0 = lane < 8 ? wcm[lane] : 0;
        a0 = warp_sum(a0); c0 = warp_sum_i(c0);
        if (lane == 0) {
            s_base = (c0 > 0) ? atomicAdd(&g_candcnt[b], c0) : 0;
            if (a0 != 0.f) atomicAdd(&g_sumbelow[b], (double)a0);
            if (blockIdx.x == 0) {
                g_sel0[b] = sel;
                g_rank2[b] = s_rankin;
                g_cntbelow[b] = s_before;   // exact from scan
            }
        }
    }
    __syncthreads();
    int cbase = s_base;
    unsigned int* cand = g_cand + (size_t)b * NMAX;

    // sweep 2 (segment is L1-hot from sweep 1): write matches contiguously
    for (int i = tid; i < cnt; i += TPB) {
        float2 pg = in[i];
        float rr = fabsf(fmaf(a, pg.x, be) - pg.y);
        unsigned bits = __float_as_uint(rr);
        if ((bits >> 21) == selu) {
            int p = atomicAdd(&s_local, 1);
            cand[cbase + p] = bits;
        }
    }
}

// ------------------------------ 5. finish ----------------------------------
#define FTPB 1024
__global__ __launch_bounds__(FTPB) void finish_kernel(float* __restrict__ out0) {
    int b = blockIdx.x;
    int tid = threadIdx.x;
    int lane = tid & 31, w = tid >> 5;
    int sel0 = g_sel0[b];
    int k = g_k[b];

    __shared__ unsigned int hist[2048];
    __shared__ int wtot[32];
    __shared__ int s_bin;
    __shared__ long long s_before;
    __shared__ double sred[32];
    __shared__ long long lred[32];

    if (sel0 < 0 || k <= 0) return;   // contributes 0 to the mean

    int m = g_candcnt[b];
    long long rw = g_rank2[b];
    const unsigned int* cand = g_cand + (size_t)b * NMAX;

    // ---- pass A: bits[20:10], 2048 bins (4x unrolled loads for MLP) ----
    for (int i = tid; i < 2048; i += FTPB) hist[i] = 0u;
    __syncthreads();
    {
        int i = tid;
        for (; i + 3*FTPB < m; i += 4*FTPB) {
            unsigned b0 = cand[i];
            unsigned b1 = cand[i + FTPB];
            unsigned b2 = cand[i + 2*FTPB];
            unsigned b3 = cand[i + 3*FTPB];
            atomicAdd(&hist[(b0 >> 10) & 2047u], 1u);
            atomicAdd(&hist[(b1 >> 10) & 2047u], 1u);
            atomicAdd(&hist[(b2 >> 10) & 2047u], 1u);
            atomicAdd(&hist[(b3 >> 10) & 2047u], 1u);
        }
        for (; i < m; i += FTPB)
            atomicAdd(&hist[(cand[i] >> 10) & 2047u], 1u);
    }
    __syncthreads();
    {
        int c0 = (int)hist[tid*2], c1 = (int)hist[tid*2+1];
        int mysum = c0 + c1;
        int incl = warp_scan_incl(mysum, lane);
        if (lane == 31) wtot[w] = incl;
        __syncthreads();
        int wbase = 0;
        for (int j = 0; j < w; j++) wbase += wtot[j];
        long long base = (long long)wbase + incl - mysum;
        if (rw >= base && rw < base + mysum) {
            if (rw < base + c0) { s_bin = tid*2;   s_before = base; }
            else                { s_bin = tid*2+1; s_before = base + c0; }
        }
        __syncthreads();
    }
    int selA = s_bin;
    rw -= s_before;
    __syncthreads();

    // ---- pass B: bits[9:0], 1024 bins (4x unrolled) ----
    for (int i = tid; i < 1024; i += FTPB) hist[i] = 0u;
    __syncthreads();
    {
        unsigned selAu = (unsigned)selA;
        int i = tid;
        for (; i + 3*FTPB < m; i += 4*FTPB) {
            unsigned b0 = cand[i];
            unsigned b1 = cand[i + FTPB];
            unsigned b2 = cand[i + 2*FTPB];
            unsigned b3 = cand[i + 3*FTPB];
            if (((b0 >> 10) & 2047u) == selAu) atomicAdd(&hist[b0 & 1023u], 1u);
            if (((b1 >> 10) & 2047u) == selAu) atomicAdd(&hist[b1 & 1023u], 1u);
            if (((b2 >> 10) & 2047u) == selAu) atomicAdd(&hist[b2 & 1023u], 1u);
            if (((b3 >> 10) & 2047u) == selAu) atomicAdd(&hist[b3 & 1023u], 1u);
        }
        for (; i < m; i += FTPB) {
            unsigned bits = cand[i];
            if (((bits >> 10) & 2047u) == selAu)
                atomicAdd(&hist[bits & 1023u], 1u);
        }
    }
    __syncthreads();
    {
        int mysum = (int)hist[tid & 1023];
        int incl = warp_scan_incl(mysum, lane);
        if (lane == 31) wtot[w] = incl;
        __syncthreads();
        int wbase = 0;
        for (int j = 0; j < w; j++) wbase += wtot[j];
        long long base = (long long)wbase + incl - mysum;
        if (rw >= base && rw < base + mysum) s_bin = tid;
        __syncthreads();
    }
    int selB = s_bin;
    unsigned v_bits = ((unsigned)sel0 << 21) | ((unsigned)selA << 10) | (unsigned)selB;
    float v = __uint_as_float(v_bits);

    // ---- pass C: sum/count of candidates strictly below v (4x unrolled) ----
    double s = 0.0;
    long long c = 0;
    {
        int i = tid;
        for (; i + 3*FTPB < m; i += 4*FTPB) {
            unsigned b0 = cand[i];
            unsigned b1 = cand[i + FTPB];
            unsigned b2 = cand[i + 2*FTPB];
            unsigned b3 = cand[i + 3*FTPB];
            if (b0 < v_bits) { s += (double)__uint_as_float(b0); c++; }
            if (b1 < v_bits) { s += (double)__uint_as_float(b1); c++; }
            if (b2 < v_bits) { s += (double)__uint_as_float(b2); c++; }
            if (b3 < v_bits) { s += (double)__uint_as_float(b3); c++; }
        }
        for (; i < m; i += FTPB) {
            unsigned bits = cand[i];
            if (bits < v_bits) { s += (double)__uint_as_float(bits); c++; }
        }
    }
    s = warp_sum_d(s);
    c = warp_sum_ll(c);
    if (lane == 0) { sred[w] = s; lred[w] = c; }
    __syncthreads();
    if (w == 0) {
        double sv = sred[lane];
        long long cv = lred[lane];
        sv = warp_sum_d(sv);
        cv = warp_sum_ll(cv);
        if (lane == 0) {
            long long total_less = g_cntbelow[b] + cv;
            double kept = g_sumbelow[b] + sv +
                          (double)((long long)k - total_less) * (double)v;
            float loss = (float)(kept / (double)k);
            atomicAdd(out0, loss / (float)BB);
        }
    }
}

// ------------------------------ launch -------------------------------------
extern "C" void kernel_launch(void* const* d_in, const int* in_sizes, int n_in,
                              void* d_out, int out_size) {
    const float* pred = (const float*)d_in[0];
    const float* gt   = (const float*)d_in[1];
    const int*   mask = (const int*)d_in[2];
    float* out = (float*)d_out;

    int total = in_sizes[0];
    int N = total / BB;

    dim3 grid(BLKX, BB);

    pack_kernel<<<grid, TPB>>>(pred, gt, mask, N);
    finalize_kernel<<<BB, TPB>>>(out);
    hist_kernel<<<grid, TPB>>>();
    compact_kernel<<<grid, TPB>>>();
    finish_kernel<<<BB, FTPB>>>(out);
}

// round 14
// speedup vs baseline: 1.2388x; 1.0196x over previous
#include <cuda_runtime.h>
#include <math.h>
#include <stdint.h>

// ---------------------------------------------------------------------------
// SSITrimLoss: masked scale/shift-invariant trimmed L1 loss.
// Pipeline (5 launches) — R13 structure; compact now SINGLE sweep with
// shared-memory staging buffer (most blocks: one global reserve + one flush):
//   1. pack      : moments + compact valid (p,g) pairs per block segment
//   2. finalize  : alpha/beta/k per sample; zero hists/counters/out
//   3. hist      : res=|a*p+b-g| from pairs, 2048-bin count hist
//   4. compact   : per-block level-0 scan (L2-hot) + ONE sweep of pairs ->
//                  below-bin sum (regs) + staged gather of in-bin candidates
//   5. finish    : 21-bit refine (ILP-4) -> atomicAdd(out, loss/B)
// Selection is bit-exact (monotone uint encoding of non-negative floats).
// ---------------------------------------------------------------------------

#define BB    32
#define NMAX  491520
#define TPB   256
#define BLKX  32
#define SEGLEN (NMAX / BLKX)
#define FULLM 0xffffffffu
#define CAP   4096          /* staging buffer entries */
#define TILE  (TPB * 8)     /* 2048 elements per tile; <= CAP - watermark */

__device__ __align__(16) float2       g_pair[(size_t)BB * NMAX];
__device__ __align__(16) unsigned int g_cand[(size_t)BB * NMAX];
__device__ float              g_part[BB][BLKX][5];
__device__ int                g_segcnt[BB][BLKX];
__device__ unsigned int       g_hcnt[BB][2048];
__device__ float              g_alpha[BB], g_beta[BB];
__device__ int                g_k[BB];
__device__ long long          g_rank[BB];     // k-1 (set by finalize)
__device__ long long          g_rank2[BB];    // rank within selected bin
__device__ int                g_sel0[BB];
__device__ double             g_sumbelow[BB];
__device__ long long          g_cntbelow[BB];
__device__ int                g_candcnt[BB];

// ------------------------- warp reduce/scan helpers ------------------------
__device__ __forceinline__ float warp_sum(float v) {
    #pragma unroll
    for (int off = 16; off; off >>= 1) v += __shfl_down_sync(FULLM, v, off);
    return v;
}
__device__ __forceinline__ double warp_sum_d(double v) {
    #pragma unroll
    for (int off = 16; off; off >>= 1) v += __shfl_down_sync(FULLM, v, off);
    return v;
}
__device__ __forceinline__ long long warp_sum_ll(long long v) {
    #pragma unroll
    for (int off = 16; off; off >>= 1) v += __shfl_down_sync(FULLM, v, off);
    return v;
}
__device__ __forceinline__ int warp_scan_incl(int v, int lane) {
    #pragma unroll
    for (int off = 1; off < 32; off <<= 1) {
        int t = __shfl_up_sync(FULLM, v, off);
        if (lane >= off) v += t;
    }
    return v;
}

// ------------------------ 1. pack (moments + gather) -----------------------
__global__ __launch_bounds__(TPB) void pack_kernel(
        const float* __restrict__ pred, const float* __restrict__ gt,
        const int* __restrict__ mask, int N) {
    int b = blockIdx.y;
    int n4 = N >> 2;
    int chunk4 = n4 / BLKX;
    int start = blockIdx.x * chunk4;
    int end   = (blockIdx.x == BLKX - 1) ? n4 : start + chunk4;

    const float4* p4 = reinterpret_cast<const float4*>(pred) + (size_t)b * n4;
    const float4* g4 = reinterpret_cast<const float4*>(gt)   + (size_t)b * n4;
    const int4*   m4 = reinterpret_cast<const int4*>(mask)   + (size_t)b * n4;
    float2* out = g_pair + (size_t)b * NMAX + (size_t)blockIdx.x * SEGLEN;

    __shared__ int s_cnt;
    if (threadIdx.x == 0) s_cnt = 0;
    __syncthreads();

    int lane = threadIdx.x & 31;
    unsigned lmask = (1u << lane) - 1u;
    float sn = 0.f, sp = 0.f, sg = 0.f, spp = 0.f, spg = 0.f;

    for (int i = start + threadIdx.x; i < end; i += TPB) {
        float4 p = p4[i]; float4 g = g4[i]; int4 m = m4[i];
        bool v0 = m.x > 0, v1 = m.y > 0, v2 = m.z > 0, v3 = m.w > 0;
        if (v0) { sn += 1.f; sp += p.x; sg += g.x; spp += p.x*p.x; spg += p.x*g.x; }
        if (v1) { sn += 1.f; sp += p.y; sg += g.y; spp += p.y*p.y; spg += p.y*g.y; }
        if (v2) { sn += 1.f; sp += p.z; sg += g.z; spp += p.z*p.z; spg += p.z*g.z; }
        if (v3) { sn += 1.f; sp += p.w; sg += g.w; spp += p.w*p.w; spg += p.w*g.w; }
        unsigned bal0 = __ballot_sync(FULLM, v0);
        unsigned bal1 = __ballot_sync(FULLM, v1);
        unsigned bal2 = __ballot_sync(FULLM, v2);
        unsigned bal3 = __ballot_sync(FULLM, v3);
        int c0   = __popc(bal0);
        int c01  = c0  + __popc(bal1);
        int c012 = c01 + __popc(bal2);
        int tot  = c012 + __popc(bal3);
        int base = 0;
        if (lane == 0 && tot) base = atomicAdd(&s_cnt, tot);
        base = __shfl_sync(FULLM, base, 0);
        if (v0) out[base        + __popc(bal0 & lmask)] = make_float2(p.x, g.x);
        if (v1) out[base + c0   + __popc(bal1 & lmask)] = make_float2(p.y, g.y);
        if (v2) out[base + c01  + __popc(bal2 & lmask)] = make_float2(p.z, g.z);
        if (v3) out[base + c012 + __popc(bal3 & lmask)] = make_float2(p.w, g.w);
    }

    sn = warp_sum(sn); sp = warp_sum(sp); sg = warp_sum(sg);
    spp = warp_sum(spp); spg = warp_sum(spg);
    __shared__ float ws[5][8];
    int w = threadIdx.x >> 5;
    if (lane == 0) { ws[0][w]=sn; ws[1][w]=sp; ws[2][w]=sg; ws[3][w]=spp; ws[4][w]=spg; }
    __syncthreads();
    if (w == 0) {
        float a0 = lane < 8 ? ws[0][lane] : 0.f;
        float a1 = lane < 8 ? ws[1][lane] : 0.f;
        float a2 = lane < 8 ? ws[2][lane] : 0.f;
        float a3 = lane < 8 ? ws[3][lane] : 0.f;
        float a4 = lane < 8 ? ws[4][lane] : 0.f;
        a0 = warp_sum(a0); a1 = warp_sum(a1); a2 = warp_sum(a2);
        a3 = warp_sum(a3); a4 = warp_sum(a4);
        if (lane == 0) {
            g_part[b][blockIdx.x][0] = a0;
            g_part[b][blockIdx.x][1] = a1;
            g_part[b][blockIdx.x][2] = a2;
            g_part[b][blockIdx.x][3] = a3;
            g_part[b][blockIdx.x][4] = a4;
            g_segcnt[b][blockIdx.x] = s_cnt;
        }
    }
}

// ------------------------------ 2. finalize --------------------------------
__global__ void finalize_kernel(float* __restrict__ out0) {
    int b = blockIdx.x;
    int tid = threadIdx.x;
    for (int i = tid; i < 2048; i += blockDim.x) g_hcnt[b][i] = 0u;
    if (tid == 0) {
        g_candcnt[b] = 0;
        g_sumbelow[b] = 0.0;
        if (b == 0) *out0 = 0.f;
    }
    if (tid < 32) {
        double v0 = (double)g_part[b][tid][0];
        double v1 = (double)g_part[b][tid][1];
        double v2 = (double)g_part[b][tid][2];
        double v3 = (double)g_part[b][tid][3];
        double v4 = (double)g_part[b][tid][4];
        v0 = warp_sum_d(v0); v1 = warp_sum_d(v1); v2 = warp_sum_d(v2);
        v3 = warp_sum_d(v3); v4 = warp_sum_d(v4);
        if (tid == 0) {
            double n  = v0;
            double ns = n < 1.0 ? 1.0 : n;
            double md = v1 / ns, mz = v2 / ns;
            double var = v3 / ns - md * md;
            double cov = v4 / ns - md * mz;
            double alpha = cov / (var + 1e-6);
            double beta  = mz - alpha * md;
            g_alpha[b] = (float)alpha;
            g_beta[b]  = (float)beta;
            int k = (int)floorf(0.8f * (float)n);   // reference-matching f32 arith
            g_k[b] = k;
            g_rank[b] = (long long)k - 1;
        }
    }
}

// ------------------------------ 3. hist ------------------------------------
__global__ __launch_bounds__(TPB) void hist_kernel() {
    int b = blockIdx.y;
    __shared__ unsigned int sh[2048];
    for (int i = threadIdx.x; i < 2048; i += TPB) sh[i] = 0u;
    __syncthreads();

    int cnt = g_segcnt[b][blockIdx.x];
    const float2* in = g_pair + (size_t)b * NMAX + (size_t)blockIdx.x * SEGLEN;
    float a = g_alpha[b], be = g_beta[b];

    for (int i = threadIdx.x; i < cnt; i += TPB) {
        float2 pg = in[i];
        float r = fabsf(fmaf(a, pg.x, be) - pg.y);
        atomicAdd(&sh[__float_as_uint(r) >> 21], 1u);
    }
    __syncthreads();
    for (int i = threadIdx.x; i < 2048; i += TPB) {
        unsigned c = sh[i];
        if (c) atomicAdd(&g_hcnt[b][i], c);
    }
}

// ---------------------- 4. compact (+level-0 select) -----------------------
// Single sweep: below-bin sum in registers, matches staged into a 4096-entry
// shared buffer, flushed with one block-wide global reserve per flush.
__global__ __launch_bounds__(TPB) void compact_kernel() {
    int b = blockIdx.y;
    int tid = threadIdx.x;
    int lane = tid & 31, w = tid >> 5;

    __shared__ unsigned int s_buf[CAP];
    __shared__ int wtot[8];
    __shared__ int s_bin;
    __shared__ long long s_before, s_rankin;
    __shared__ int s_local, s_gbase;

    if (tid == 0) { s_bin = -1; s_local = 0; }
    long long r = g_rank[b];      // k-1; finalize-owned
    __syncthreads();

    // level-0 selection scan over 2048 bins (identical in every block; L2-hot)
    unsigned int c[8];
    int mysum = 0;
    #pragma unroll
    for (int j = 0; j < 8; j++) { c[j] = g_hcnt[b][tid*8+j]; mysum += (int)c[j]; }
    int incl = warp_scan_incl(mysum, lane);
    if (lane == 31) wtot[w] = incl;
    __syncthreads();
    int wbase = 0;
    #pragma unroll
    for (int j = 0; j < 8; j++) wbase += (j < w) ? wtot[j] : 0;
    long long base = (long long)wbase + incl - mysum;
    if (r >= 0 && r >= base && r < base + mysum) {
        long long cum = base;
        #pragma unroll
        for (int j = 0; j < 8; j++) {
            if (r < cum + (long long)c[j]) {
                s_bin = tid*8+j; s_before = cum; s_rankin = r - cum; break;
            }
            cum += (long long)c[j];
        }
    }
    __syncthreads();

    int sel = s_bin;
    if (sel < 0) {                        // k == 0 case
        if (tid == 0 && blockIdx.x == 0) g_sel0[b] = -1;
        return;
    }
    unsigned selu = (unsigned)sel;
    if (tid == 0 && blockIdx.x == 0) {
        g_sel0[b] = sel;
        g_rank2[b] = s_rankin;
        g_cntbelow[b] = s_before;   // exact from scan
    }

    int cnt = g_segcnt[b][blockIdx.x];
    const float2* in = g_pair + (size_t)b * NMAX + (size_t)blockIdx.x * SEGLEN;
    unsigned int* cand = g_cand + (size_t)b * NMAX;
    float a = g_alpha[b], be = g_beta[b];

    float sbelow = 0.f;
    // single sweep in tiles of TILE elements; flush buffer when it could overflow
    for (int t0 = 0; t0 < cnt; t0 += TILE) {
        int tend = t0 + TILE < cnt ? t0 + TILE : cnt;
        for (int i = t0 + tid; i < tend; i += TPB) {
            float2 pg = in[i];
            float rr = fabsf(fmaf(a, pg.x, be) - pg.y);
            unsigned bits = __float_as_uint(rr);
            unsigned top = bits >> 21;
            if (top < selu) sbelow += rr;
            else if (top == selu) s_buf[atomicAdd(&s_local, 1)] = bits;
        }
        // flush if next tile could overflow
        if (t0 + TILE < cnt) {
            __syncthreads();
            int nloc = s_local;
            if (nloc + TILE > CAP) {
                if (tid == 0) {
                    s_gbase = atomicAdd(&g_candcnt[b], nloc);
                    s_local = 0;
                }
                __syncthreads();
                int gb = s_gbase;
                for (int i = tid; i < nloc; i += TPB) cand[gb + i] = s_buf[i];
                __syncthreads();
            }
        }
    }
    // final flush
    __syncthreads();
    {
        int nloc = s_local;
        if (nloc > 0) {
            if (tid == 0) s_gbase = atomicAdd(&g_candcnt[b], nloc);
            __syncthreads();
            int gb = s_gbase;
            for (int i = tid; i < nloc; i += TPB) cand[gb + i] = s_buf[i];
        }
    }

    // block-reduce below-bin sum
    float sb = warp_sum(sbelow);
    __shared__ float wsum[8];
    if (lane == 0) wsum[w] = sb;
    __syncthreads();
    if (tid == 0) {
        float tot = 0.f;
        #pragma unroll
        for (int j = 0; j < 8; j++) tot += wsum[j];
        if (tot != 0.f) atomicAdd(&g_sumbelow[b], (double)tot);
    }
}

// ------------------------------ 5. finish ----------------------------------
#define FTPB 1024
__global__ __launch_bounds__(FTPB) void finish_kernel(float* __restrict__ out0) {
    int b = blockIdx.x;
    int tid = threadIdx.x;
    int lane = tid & 31, w = tid >> 5;
    int sel0 = g_sel0[b];
    int k = g_k[b];

    __shared__ unsigned int hist[2048];
    __shared__ int wtot[32];
    __shared__ int s_bin;
    __shared__ long long s_before;
    __shared__ double sred[32];
    __shared__ long long lred[32];

    if (sel0 < 0 || k <= 0) return;   // contributes 0 to the mean

    int m = g_candcnt[b];
    long long rw = g_rank2[b];
    const unsigned int* cand = g_cand + (size_t)b * NMAX;

    // ---- pass A: bits[20:10], 2048 bins (4x unrolled loads for MLP) ----
    for (int i = tid; i < 2048; i += FTPB) hist[i] = 0u;
    __syncthreads();
    {
        int i = tid;
        for (; i + 3*FTPB < m; i += 4*FTPB) {
            unsigned b0 = cand[i];
            unsigned b1 = cand[i + FTPB];
            unsigned b2 = cand[i + 2*FTPB];
            unsigned b3 = cand[i + 3*FTPB];
            atomicAdd(&hist[(b0 >> 10) & 2047u], 1u);
            atomicAdd(&hist[(b1 >> 10) & 2047u], 1u);
            atomicAdd(&hist[(b2 >> 10) & 2047u], 1u);
            atomicAdd(&hist[(b3 >> 10) & 2047u], 1u);
        }
        for (; i < m; i += FTPB)
            atomicAdd(&hist[(cand[i] >> 10) & 2047u], 1u);
    }
    __syncthreads();
    {
        int c0 = (int)hist[tid*2], c1 = (int)hist[tid*2+1];
        int mysum = c0 + c1;
        int incl = warp_scan_incl(mysum, lane);
        if (lane == 31) wtot[w] = incl;
        __syncthreads();
        int wbase = 0;
        for (int j = 0; j < w; j++) wbase += wtot[j];
        long long base = (long long)wbase + incl - mysum;
        if (rw >= base && rw < base + mysum) {
            if (rw < base + c0) { s_bin = tid*2;   s_before = base; }
            else                { s_bin = tid*2+1; s_before = base + c0; }
        }
        __syncthreads();
    }
    int selA = s_bin;
    rw -= s_before;
    __syncthreads();

    // ---- pass B: bits[9:0], 1024 bins (4x unrolled) ----
    for (int i = tid; i < 1024; i += FTPB) hist[i] = 0u;
    __syncthreads();
    {
        unsigned selAu = (unsigned)selA;
        int i = tid;
        for (; i + 3*FTPB < m; i += 4*FTPB) {
            unsigned b0 = cand[i];
            unsigned b1 = cand[i + FTPB];
            unsigned b2 = cand[i + 2*FTPB];
            unsigned b3 = cand[i + 3*FTPB];
            if (((b0 >> 10) & 2047u) == selAu) atomicAdd(&hist[b0 & 1023u], 1u);
            if (((b1 >> 10) & 2047u) == selAu) atomicAdd(&hist[b1 & 1023u], 1u);
            if (((b2 >> 10) & 2047u) == selAu) atomicAdd(&hist[b2 & 1023u], 1u);
            if (((b3 >> 10) & 2047u) == selAu) atomicAdd(&hist[b3 & 1023u], 1u);
        }
        for (; i < m; i += FTPB) {
            unsigned bits = cand[i];
            if (((bits >> 10) & 2047u) == selAu)
                atomicAdd(&hist[bits & 1023u], 1u);
        }
    }
    __syncthreads();
    {
        int mysum = (int)hist[tid & 1023];
        int incl = warp_scan_incl(mysum, lane);
        if (lane == 31) wtot[w] = incl;
        __syncthreads();
        int wbase = 0;
        for (int j = 0; j < w; j++) wbase += wtot[j];
        long long base = (long long)wbase + incl - mysum;
        if (rw >= base && rw < base + mysum) s_bin = tid;
        __syncthreads();
    }
    int selB = s_bin;
    unsigned v_bits = ((unsigned)sel0 << 21) | ((unsigned)selA << 10) | (unsigned)selB;
    float v = __uint_as_float(v_bits);

    // ---- pass C: sum/count of candidates strictly below v (4x unrolled) ----
    double s = 0.0;
    long long c = 0;
    {
        int i = tid;
        for (; i + 3*FTPB < m; i += 4*FTPB) {
            unsigned b0 = cand[i];
            unsigned b1 = cand[i + FTPB];
            unsigned b2 = cand[i + 2*FTPB];
            unsigned b3 = cand[i + 3*FTPB];
            if (b0 < v_bits) { s += (double)__uint_as_float(b0); c++; }
            if (b1 < v_bits) { s += (double)__uint_as_float(b1); c++; }
            if (b2 < v_bits) { s += (double)__uint_as_float(b2); c++; }
            if (b3 < v_bits) { s += (double)__uint_as_float(b3); c++; }
        }
        for (; i < m; i += FTPB) {
            unsigned bits = cand[i];
            if (bits < v_bits) { s += (double)__uint_as_float(bits); c++; }
        }
    }
    s = warp_sum_d(s);
    c = warp_sum_ll(c);
    if (lane == 0) { sred[w] = s; lred[w] = c; }
    __syncthreads();
    if (w == 0) {
        double sv = sred[lane];
        long long cv = lred[lane];
        sv = warp_sum_d(sv);
        cv = warp_sum_ll(cv);
        if (lane == 0) {
            long long total_less = g_cntbelow[b] + cv;
            double kept = g_sumbelow[b] + sv +
                          (double)((long long)k - total_less) * (double)v;
            float loss = (float)(kept / (double)k);
            atomicAdd(out0, loss / (float)BB);
        }
    }
}

// ------------------------------ launch -------------------------------------
extern "C" void kernel_launch(void* const* d_in, const int* in_sizes, int n_in,
                              void* d_out, int out_size) {
    const float* pred = (const float*)d_in[0];
    const float* gt   = (const float*)d_in[1];
    const int*   mask = (const int*)d_in[2];
    float* out = (float*)d_out;

    int total = in_sizes[0];
    int N = total / BB;

    dim3 grid(BLKX, BB);

    pack_kernel<<<grid, TPB>>>(pred, gt, mask, N);
    finalize_kernel<<<BB, TPB>>>(out);
    hist_kernel<<<grid, TPB>>>();
    compact_kernel<<<grid, TPB>>>();
    finish_kernel<<<BB, FTPB>>>(out);
}

// round 15
// speedup vs baseline: 1.2446x; 1.0047x over previous
#include <cuda_runtime.h>
#include <math.h>
#include <stdint.h>

// ---------------------------------------------------------------------------
// SSITrimLoss: masked scale/shift-invariant trimmed L1 loss.
// Pipeline (5 launches) — R14 structure; ILP-4 loads in hist + compact sweeps
// (same MLP fix that won in finish at R10):
//   1. pack      : moments + compact valid (p,g) pairs per block segment
//   2. finalize  : alpha/beta/k per sample; zero hists/counters/out
//   3. hist      : res=|a*p+b-g| from pairs, 2048-bin count hist (ILP-4)
//   4. compact   : per-block level-0 scan + ONE sweep (ILP-4) of pairs ->
//                  below-bin sum (regs) + staged gather of in-bin candidates
//   5. finish    : 21-bit refine (ILP-4) -> atomicAdd(out, loss/B)
// Selection is bit-exact (monotone uint encoding of non-negative floats).
// ---------------------------------------------------------------------------

#define BB    32
#define NMAX  491520
#define TPB   256
#define BLKX  32
#define SEGLEN (NMAX / BLKX)
#define FULLM 0xffffffffu
#define CAP   4096          /* staging buffer entries */
#define TILE  (TPB * 8)     /* 2048 elements per tile */

__device__ __align__(16) float2       g_pair[(size_t)BB * NMAX];
__device__ __align__(16) unsigned int g_cand[(size_t)BB * NMAX];
__device__ float              g_part[BB][BLKX][5];
__device__ int                g_segcnt[BB][BLKX];
__device__ unsigned int       g_hcnt[BB][2048];
__device__ float              g_alpha[BB], g_beta[BB];
__device__ int                g_k[BB];
__device__ long long          g_rank[BB];     // k-1 (set by finalize)
__device__ long long          g_rank2[BB];    // rank within selected bin
__device__ int                g_sel0[BB];
__device__ double             g_sumbelow[BB];
__device__ long long          g_cntbelow[BB];
__device__ int                g_candcnt[BB];

// ------------------------- warp reduce/scan helpers ------------------------
__device__ __forceinline__ float warp_sum(float v) {
    #pragma unroll
    for (int off = 16; off; off >>= 1) v += __shfl_down_sync(FULLM, v, off);
    return v;
}
__device__ __forceinline__ double warp_sum_d(double v) {
    #pragma unroll
    for (int off = 16; off; off >>= 1) v += __shfl_down_sync(FULLM, v, off);
    return v;
}
__device__ __forceinline__ long long warp_sum_ll(long long v) {
    #pragma unroll
    for (int off = 16; off; off >>= 1) v += __shfl_down_sync(FULLM, v, off);
    return v;
}
__device__ __forceinline__ int warp_scan_incl(int v, int lane) {
    #pragma unroll
    for (int off = 1; off < 32; off <<= 1) {
        int t = __shfl_up_sync(FULLM, v, off);
        if (lane >= off) v += t;
    }
    return v;
}

// ------------------------ 1. pack (moments + gather) -----------------------
__global__ __launch_bounds__(TPB) void pack_kernel(
        const float* __restrict__ pred, const float* __restrict__ gt,
        const int* __restrict__ mask, int N) {
    int b = blockIdx.y;
    int n4 = N >> 2;
    int chunk4 = n4 / BLKX;
    int start = blockIdx.x * chunk4;
    int end   = (blockIdx.x == BLKX - 1) ? n4 : start + chunk4;

    const float4* p4 = reinterpret_cast<const float4*>(pred) + (size_t)b * n4;
    const float4* g4 = reinterpret_cast<const float4*>(gt)   + (size_t)b * n4;
    const int4*   m4 = reinterpret_cast<const int4*>(mask)   + (size_t)b * n4;
    float2* out = g_pair + (size_t)b * NMAX + (size_t)blockIdx.x * SEGLEN;

    __shared__ int s_cnt;
    if (threadIdx.x == 0) s_cnt = 0;
    __syncthreads();

    int lane = threadIdx.x & 31;
    unsigned lmask = (1u << lane) - 1u;
    float sn = 0.f, sp = 0.f, sg = 0.f, spp = 0.f, spg = 0.f;

    for (int i = start + threadIdx.x; i < end; i += TPB) {
        float4 p = p4[i]; float4 g = g4[i]; int4 m = m4[i];
        bool v0 = m.x > 0, v1 = m.y > 0, v2 = m.z > 0, v3 = m.w > 0;
        if (v0) { sn += 1.f; sp += p.x; sg += g.x; spp += p.x*p.x; spg += p.x*g.x; }
        if (v1) { sn += 1.f; sp += p.y; sg += g.y; spp += p.y*p.y; spg += p.y*g.y; }
        if (v2) { sn += 1.f; sp += p.z; sg += g.z; spp += p.z*p.z; spg += p.z*g.z; }
        if (v3) { sn += 1.f; sp += p.w; sg += g.w; spp += p.w*p.w; spg += p.w*g.w; }
        unsigned bal0 = __ballot_sync(FULLM, v0);
        unsigned bal1 = __ballot_sync(FULLM, v1);
        unsigned bal2 = __ballot_sync(FULLM, v2);
        unsigned bal3 = __ballot_sync(FULLM, v3);
        int c0   = __popc(bal0);
        int c01  = c0  + __popc(bal1);
        int c012 = c01 + __popc(bal2);
        int tot  = c012 + __popc(bal3);
        int base = 0;
        if (lane == 0 && tot) base = atomicAdd(&s_cnt, tot);
        base = __shfl_sync(FULLM, base, 0);
        if (v0) out[base        + __popc(bal0 & lmask)] = make_float2(p.x, g.x);
        if (v1) out[base + c0   + __popc(bal1 & lmask)] = make_float2(p.y, g.y);
        if (v2) out[base + c01  + __popc(bal2 & lmask)] = make_float2(p.z, g.z);
        if (v3) out[base + c012 + __popc(bal3 & lmask)] = make_float2(p.w, g.w);
    }

    sn = warp_sum(sn); sp = warp_sum(sp); sg = warp_sum(sg);
    spp = warp_sum(spp); spg = warp_sum(spg);
    __shared__ float ws[5][8];
    int w = threadIdx.x >> 5;
    if (lane == 0) { ws[0][w]=sn; ws[1][w]=sp; ws[2][w]=sg; ws[3][w]=spp; ws[4][w]=spg; }
    __syncthreads();
    if (w == 0) {
        float a0 = lane < 8 ? ws[0][lane] : 0.f;
        float a1 = lane < 8 ? ws[1][lane] : 0.f;
        float a2 = lane < 8 ? ws[2][lane] : 0.f;
        float a3 = lane < 8 ? ws[3][lane] : 0.f;
        float a4 = lane < 8 ? ws[4][lane] : 0.f;
        a0 = warp_sum(a0); a1 = warp_sum(a1); a2 = warp_sum(a2);
        a3 = warp_sum(a3); a4 = warp_sum(a4);
        if (lane == 0) {
            g_part[b][blockIdx.x][0] = a0;
            g_part[b][blockIdx.x][1] = a1;
            g_part[b][blockIdx.x][2] = a2;
            g_part[b][blockIdx.x][3] = a3;
            g_part[b][blockIdx.x][4] = a4;
            g_segcnt[b][blockIdx.x] = s_cnt;
        }
    }
}

// ------------------------------ 2. finalize --------------------------------
__global__ void finalize_kernel(float* __restrict__ out0) {
    int b = blockIdx.x;
    int tid = threadIdx.x;
    for (int i = tid; i < 2048; i += blockDim.x) g_hcnt[b][i] = 0u;
    if (tid == 0) {
        g_candcnt[b] = 0;
        g_sumbelow[b] = 0.0;
        if (b == 0) *out0 = 0.f;
    }
    if (tid < 32) {
        double v0 = (double)g_part[b][tid][0];
        double v1 = (double)g_part[b][tid][1];
        double v2 = (double)g_part[b][tid][2];
        double v3 = (double)g_part[b][tid][3];
        double v4 = (double)g_part[b][tid][4];
        v0 = warp_sum_d(v0); v1 = warp_sum_d(v1); v2 = warp_sum_d(v2);
        v3 = warp_sum_d(v3); v4 = warp_sum_d(v4);
        if (tid == 0) {
            double n  = v0;
            double ns = n < 1.0 ? 1.0 : n;
            double md = v1 / ns, mz = v2 / ns;
            double var = v3 / ns - md * md;
            double cov = v4 / ns - md * mz;
            double alpha = cov / (var + 1e-6);
            double beta  = mz - alpha * md;
            g_alpha[b] = (float)alpha;
            g_beta[b]  = (float)beta;
            int k = (int)floorf(0.8f * (float)n);   // reference-matching f32 arith
            g_k[b] = k;
            g_rank[b] = (long long)k - 1;
        }
    }
}

// ------------------------------ 3. hist ------------------------------------
__global__ __launch_bounds__(TPB) void hist_kernel() {
    int b = blockIdx.y;
    __shared__ unsigned int sh[2048];
    for (int i = threadIdx.x; i < 2048; i += TPB) sh[i] = 0u;
    __syncthreads();

    int cnt = g_segcnt[b][blockIdx.x];
    const float2* in = g_pair + (size_t)b * NMAX + (size_t)blockIdx.x * SEGLEN;
    float a = g_alpha[b], be = g_beta[b];

    int i = threadIdx.x;
    for (; i + 3*TPB < cnt; i += 4*TPB) {
        float2 q0 = in[i];
        float2 q1 = in[i + TPB];
        float2 q2 = in[i + 2*TPB];
        float2 q3 = in[i + 3*TPB];
        float r0 = fabsf(fmaf(a, q0.x, be) - q0.y);
        float r1 = fabsf(fmaf(a, q1.x, be) - q1.y);
        float r2 = fabsf(fmaf(a, q2.x, be) - q2.y);
        float r3 = fabsf(fmaf(a, q3.x, be) - q3.y);
        atomicAdd(&sh[__float_as_uint(r0) >> 21], 1u);
        atomicAdd(&sh[__float_as_uint(r1) >> 21], 1u);
        atomicAdd(&sh[__float_as_uint(r2) >> 21], 1u);
        atomicAdd(&sh[__float_as_uint(r3) >> 21], 1u);
    }
    for (; i < cnt; i += TPB) {
        float2 pg = in[i];
        float r = fabsf(fmaf(a, pg.x, be) - pg.y);
        atomicAdd(&sh[__float_as_uint(r) >> 21], 1u);
    }
    __syncthreads();
    for (int j = threadIdx.x; j < 2048; j += TPB) {
        unsigned c = sh[j];
        if (c) atomicAdd(&g_hcnt[b][j], c);
    }
}

// ---------------------- 4. compact (+level-0 select) -----------------------
__global__ __launch_bounds__(TPB) void compact_kernel() {
    int b = blockIdx.y;
    int tid = threadIdx.x;
    int lane = tid & 31, w = tid >> 5;

    __shared__ unsigned int s_buf[CAP];
    __shared__ int wtot[8];
    __shared__ int s_bin;
    __shared__ long long s_before, s_rankin;
    __shared__ int s_local, s_gbase;

    if (tid == 0) { s_bin = -1; s_local = 0; }
    long long r = g_rank[b];      // k-1; finalize-owned
    __syncthreads();

    // level-0 selection scan over 2048 bins (identical in every block; L2-hot)
    unsigned int c[8];
    int mysum = 0;
    #pragma unroll
    for (int j = 0; j < 8; j++) { c[j] = g_hcnt[b][tid*8+j]; mysum += (int)c[j]; }
    int incl = warp_scan_incl(mysum, lane);
    if (lane == 31) wtot[w] = incl;
    __syncthreads();
    int wbase = 0;
    #pragma unroll
    for (int j = 0; j < 8; j++) wbase += (j < w) ? wtot[j] : 0;
    long long base = (long long)wbase + incl - mysum;
    if (r >= 0 && r >= base && r < base + mysum) {
        long long cum = base;
        #pragma unroll
        for (int j = 0; j < 8; j++) {
            if (r < cum + (long long)c[j]) {
                s_bin = tid*8+j; s_before = cum; s_rankin = r - cum; break;
            }
            cum += (long long)c[j];
        }
    }
    __syncthreads();

    int sel = s_bin;
    if (sel < 0) {                        // k == 0 case
        if (tid == 0 && blockIdx.x == 0) g_sel0[b] = -1;
        return;
    }
    unsigned selu = (unsigned)sel;
    if (tid == 0 && blockIdx.x == 0) {
        g_sel0[b] = sel;
        g_rank2[b] = s_rankin;
        g_cntbelow[b] = s_before;   // exact from scan
    }

    int cnt = g_segcnt[b][blockIdx.x];
    const float2* in = g_pair + (size_t)b * NMAX + (size_t)blockIdx.x * SEGLEN;
    unsigned int* cand = g_cand + (size_t)b * NMAX;
    float a = g_alpha[b], be = g_beta[b];

    float sbelow = 0.f;
    // single sweep in tiles; ILP-4 loads inside each tile; flush on watermark
    for (int t0 = 0; t0 < cnt; t0 += TILE) {
        int tend = t0 + TILE < cnt ? t0 + TILE : cnt;
        int i = t0 + tid;
        for (; i + 3*TPB < tend; i += 4*TPB) {
            float2 q0 = in[i];
            float2 q1 = in[i + TPB];
            float2 q2 = in[i + 2*TPB];
            float2 q3 = in[i + 3*TPB];
            float r0 = fabsf(fmaf(a, q0.x, be) - q0.y);
            float r1 = fabsf(fmaf(a, q1.x, be) - q1.y);
            float r2 = fabsf(fmaf(a, q2.x, be) - q2.y);
            float r3 = fabsf(fmaf(a, q3.x, be) - q3.y);
            unsigned b0 = __float_as_uint(r0), t0b = b0 >> 21;
            unsigned b1 = __float_as_uint(r1), t1b = b1 >> 21;
            unsigned b2 = __float_as_uint(r2), t2b = b2 >> 21;
            unsigned b3 = __float_as_uint(r3), t3b = b3 >> 21;
            if (t0b < selu) sbelow += r0;
            else if (t0b == selu) s_buf[atomicAdd(&s_local, 1)] = b0;
            if (t1b < selu) sbelow += r1;
            else if (t1b == selu) s_buf[atomicAdd(&s_local, 1)] = b1;
            if (t2b < selu) sbelow += r2;
            else if (t2b == selu) s_buf[atomicAdd(&s_local, 1)] = b2;
            if (t3b < selu) sbelow += r3;
            else if (t3b == selu) s_buf[atomicAdd(&s_local, 1)] = b3;
        }
        for (; i < tend; i += TPB) {
            float2 pg = in[i];
            float rr = fabsf(fmaf(a, pg.x, be) - pg.y);
            unsigned bits = __float_as_uint(rr);
            unsigned top = bits >> 21;
            if (top < selu) sbelow += rr;
            else if (top == selu) s_buf[atomicAdd(&s_local, 1)] = bits;
        }
        // flush if next tile could overflow
        if (t0 + TILE < cnt) {
            __syncthreads();
            int nloc = s_local;
            if (nloc + TILE > CAP) {
                if (tid == 0) {
                    s_gbase = atomicAdd(&g_candcnt[b], nloc);
                    s_local = 0;
                }
                __syncthreads();
                int gb = s_gbase;
                for (int j = tid; j < nloc; j += TPB) cand[gb + j] = s_buf[j];
                __syncthreads();
            }
        }
    }
    // final flush
    __syncthreads();
    {
        int nloc = s_local;
        if (nloc > 0) {
            if (tid == 0) s_gbase = atomicAdd(&g_candcnt[b], nloc);
            __syncthreads();
            int gb = s_gbase;
            for (int j = tid; j < nloc; j += TPB) cand[gb + j] = s_buf[j];
        }
    }

    // block-reduce below-bin sum
    float sb = warp_sum(sbelow);
    __shared__ float wsum[8];
    if (lane == 0) wsum[w] = sb;
    __syncthreads();
    if (tid == 0) {
        float tot = 0.f;
        #pragma unroll
        for (int j = 0; j < 8; j++) tot += wsum[j];
        if (tot != 0.f) atomicAdd(&g_sumbelow[b], (double)tot);
    }
}

// ------------------------------ 5. finish ----------------------------------
#define FTPB 1024
__global__ __launch_bounds__(FTPB) void finish_kernel(float* __restrict__ out0) {
    int b = blockIdx.x;
    int tid = threadIdx.x;
    int lane = tid & 31, w = tid >> 5;
    int sel0 = g_sel0[b];
    int k = g_k[b];

    __shared__ unsigned int hist[2048];
    __shared__ int wtot[32];
    __shared__ int s_bin;
    __shared__ long long s_before;
    __shared__ double sred[32];
    __shared__ long long lred[32];

    if (sel0 < 0 || k <= 0) return;   // contributes 0 to the mean

    int m = g_candcnt[b];
    long long rw = g_rank2[b];
    const unsigned int* cand = g_cand + (size_t)b * NMAX;

    // ---- pass A: bits[20:10], 2048 bins (4x unrolled loads for MLP) ----
    for (int i = tid; i < 2048; i += FTPB) hist[i] = 0u;
    __syncthreads();
    {
        int i = tid;
        for (; i + 3*FTPB < m; i += 4*FTPB) {
            unsigned b0 = cand[i];
            unsigned b1 = cand[i + FTPB];
            unsigned b2 = cand[i + 2*FTPB];
            unsigned b3 = cand[i + 3*FTPB];
            atomicAdd(&hist[(b0 >> 10) & 2047u], 1u);
            atomicAdd(&hist[(b1 >> 10) & 2047u], 1u);
            atomicAdd(&hist[(b2 >> 10) & 2047u], 1u);
            atomicAdd(&hist[(b3 >> 10) & 2047u], 1u);
        }
        for (; i < m; i += FTPB)
            atomicAdd(&hist[(cand[i] >> 10) & 2047u], 1u);
    }
    __syncthreads();
    {
        int c0 = (int)hist[tid*2], c1 = (int)hist[tid*2+1];
        int mysum = c0 + c1;
        int incl = warp_scan_incl(mysum, lane);
        if (lane == 31) wtot[w] = incl;
        __syncthreads();
        int wbase = 0;
        for (int j = 0; j < w; j++) wbase += wtot[j];
        long long base = (long long)wbase + incl - mysum;
        if (rw >= base && rw < base + mysum) {
            if (rw < base + c0) { s_bin = tid*2;   s_before = base; }
            else                { s_bin = tid*2+1; s_before = base + c0; }
        }
        __syncthreads();
    }
    int selA = s_bin;
    rw -= s_before;
    __syncthreads();

    // ---- pass B: bits[9:0], 1024 bins (4x unrolled) ----
    for (int i = tid; i < 1024; i += FTPB) hist[i] = 0u;
    __syncthreads();
    {
        unsigned selAu = (unsigned)selA;
        int i = tid;
        for (; i + 3*FTPB < m; i += 4*FTPB) {
            unsigned b0 = cand[i];
            unsigned b1 = cand[i + FTPB];
            unsigned b2 = cand[i + 2*FTPB];
            unsigned b3 = cand[i + 3*FTPB];
            if (((b0 >> 10) & 2047u) == selAu) atomicAdd(&hist[b0 & 1023u], 1u);
            if (((b1 >> 10) & 2047u) == selAu) atomicAdd(&hist[b1 & 1023u], 1u);
            if (((b2 >> 10) & 2047u) == selAu) atomicAdd(&hist[b2 & 1023u], 1u);
            if (((b3 >> 10) & 2047u) == selAu) atomicAdd(&hist[b3 & 1023u], 1u);
        }
        for (; i < m; i += FTPB) {
            unsigned bits = cand[i];
            if (((bits >> 10) & 2047u) == selAu)
                atomicAdd(&hist[bits & 1023u], 1u);
        }
    }
    __syncthreads();
    {
        int mysum = (int)hist[tid & 1023];
        int incl = warp_scan_incl(mysum, lane);
        if (lane == 31) wtot[w] = incl;
        __syncthreads();
        int wbase = 0;
        for (int j = 0; j < w; j++) wbase += wtot[j];
        long long base = (long long)wbase + incl - mysum;
        if (rw >= base && rw < base + mysum) s_bin = tid;
        __syncthreads();
    }
    int selB = s_bin;
    unsigned v_bits = ((unsigned)sel0 << 21) | ((unsigned)selA << 10) | (unsigned)selB;
    float v = __uint_as_float(v_bits);

    // ---- pass C: sum/count of candidates strictly below v (4x unrolled) ----
    double s = 0.0;
    long long c = 0;
    {
        int i = tid;
        for (; i + 3*FTPB < m; i += 4*FTPB) {
            unsigned b0 = cand[i];
            unsigned b1 = cand[i + FTPB];
            unsigned b2 = cand[i + 2*FTPB];
            unsigned b3 = cand[i + 3*FTPB];
            if (b0 < v_bits) { s += (double)__uint_as_float(b0); c++; }
            if (b1 < v_bits) { s += (double)__uint_as_float(b1); c++; }
            if (b2 < v_bits) { s += (double)__uint_as_float(b2); c++; }
            if (b3 < v_bits) { s += (double)__uint_as_float(b3); c++; }
        }
        for (; i < m; i += FTPB) {
            unsigned bits = cand[i];
            if (bits < v_bits) { s += (double)__uint_as_float(bits); c++; }
        }
    }
    s = warp_sum_d(s);
    c = warp_sum_ll(c);
    if (lane == 0) { sred[w] = s; lred[w] = c; }
    __syncthreads();
    if (w == 0) {
        double sv = sred[lane];
        long long cv = lred[lane];
        sv = warp_sum_d(sv);
        cv = warp_sum_ll(cv);
        if (lane == 0) {
            long long total_less = g_cntbelow[b] + cv;
            double kept = g_sumbelow[b] + sv +
                          (double)((long long)k - total_less) * (double)v;
            float loss = (float)(kept / (double)k);
            atomicAdd(out0, loss / (float)BB);
        }
    }
}

// ------------------------------ launch -------------------------------------
extern "C" void kernel_launch(void* const* d_in, const int* in_sizes, int n_in,
                              void* d_out, int out_size) {
    const float* pred = (const float*)d_in[0];
    const float* gt   = (const float*)d_in[1];
    const int*   mask = (const int*)d_in[2];
    float* out = (float*)d_out;

    int total = in_sizes[0];
    int N = total / BB;

    dim3 grid(BLKX, BB);

    pack_kernel<<<grid, TPB>>>(pred, gt, mask, N);
    finalize_kernel<<<BB, TPB>>>(out);
    hist_kernel<<<grid, TPB>>>();
    compact_kernel<<<grid, TPB>>>();
    finish_kernel<<<BB, FTPB>>>(out);
}

// round 16
// speedup vs baseline: 1.4398x; 1.1568x over previous
#include <cuda_runtime.h>
#include <math.h>
#include <stdint.h>

// ---------------------------------------------------------------------------
// SSITrimLoss: masked scale/shift-invariant trimmed L1 loss.
// Pipeline (5 launches) — R15 structure; pack uses __ldcs streaming reads
// (keeps pair array L2-resident for hist/compact) + ILP-2 main loop:
//   1. pack      : moments + compact valid (p,g) pairs per block segment
//   2. finalize  : alpha/beta/k per sample; zero hists/counters/out
//   3. hist      : res=|a*p+b-g| from pairs, 2048-bin count hist (ILP-4)
//   4. compact   : per-block level-0 scan + ONE sweep (ILP-4) of pairs ->
//                  below-bin sum (regs) + staged gather of in-bin candidates
//   5. finish    : 21-bit refine (ILP-4) -> atomicAdd(out, loss/B)
// Selection is bit-exact (monotone uint encoding of non-negative floats).
// ---------------------------------------------------------------------------

#define BB    32
#define NMAX  491520
#define TPB   256
#define BLKX  32
#define SEGLEN (NMAX / BLKX)
#define FULLM 0xffffffffu
#define CAP   4096          /* staging buffer entries */
#define TILE  (TPB * 8)     /* 2048 elements per tile */

__device__ __align__(16) float2       g_pair[(size_t)BB * NMAX];
__device__ __align__(16) unsigned int g_cand[(size_t)BB * NMAX];
__device__ float              g_part[BB][BLKX][5];
__device__ int                g_segcnt[BB][BLKX];
__device__ unsigned int       g_hcnt[BB][2048];
__device__ float              g_alpha[BB], g_beta[BB];
__device__ int                g_k[BB];
__device__ long long          g_rank[BB];     // k-1 (set by finalize)
__device__ long long          g_rank2[BB];    // rank within selected bin
__device__ int                g_sel0[BB];
__device__ double             g_sumbelow[BB];
__device__ long long          g_cntbelow[BB];
__device__ int                g_candcnt[BB];

// ------------------------- warp reduce/scan helpers ------------------------
__device__ __forceinline__ float warp_sum(float v) {
    #pragma unroll
    for (int off = 16; off; off >>= 1) v += __shfl_down_sync(FULLM, v, off);
    return v;
}
__device__ __forceinline__ double warp_sum_d(double v) {
    #pragma unroll
    for (int off = 16; off; off >>= 1) v += __shfl_down_sync(FULLM, v, off);
    return v;
}
__device__ __forceinline__ long long warp_sum_ll(long long v) {
    #pragma unroll
    for (int off = 16; off; off >>= 1) v += __shfl_down_sync(FULLM, v, off);
    return v;
}
__device__ __forceinline__ int warp_scan_incl(int v, int lane) {
    #pragma unroll
    for (int off = 1; off < 32; off <<= 1) {
        int t = __shfl_up_sync(FULLM, v, off);
        if (lane >= off) v += t;
    }
    return v;
}

// ------------------------ 1. pack (moments + gather) -----------------------
__global__ __launch_bounds__(TPB) void pack_kernel(
        const float* __restrict__ pred, const float* __restrict__ gt,
        const int* __restrict__ mask, int N) {
    int b = blockIdx.y;
    int n4 = N >> 2;
    int chunk4 = n4 / BLKX;
    int start = blockIdx.x * chunk4;
    int end   = (blockIdx.x == BLKX - 1) ? n4 : start + chunk4;

    const float4* p4 = reinterpret_cast<const float4*>(pred) + (size_t)b * n4;
    const float4* g4 = reinterpret_cast<const float4*>(gt)   + (size_t)b * n4;
    const int4*   m4 = reinterpret_cast<const int4*>(mask)   + (size_t)b * n4;
    float2* out = g_pair + (size_t)b * NMAX + (size_t)blockIdx.x * SEGLEN;

    __shared__ int s_cnt;
    if (threadIdx.x == 0) s_cnt = 0;
    __syncthreads();

    int lane = threadIdx.x & 31;
    unsigned lmask = (1u << lane) - 1u;
    float sn = 0.f, sp = 0.f, sg = 0.f, spp = 0.f, spg = 0.f;

    int i = start + threadIdx.x;
    // ILP-2: two independent (p,g,m) triples in flight; streaming loads.
    for (; i + TPB < end; i += 2*TPB) {
        float4 pA = __ldcs(&p4[i]);
        float4 gA = __ldcs(&g4[i]);
        int4   mA = __ldcs(&m4[i]);
        float4 pB = __ldcs(&p4[i + TPB]);
        float4 gB = __ldcs(&g4[i + TPB]);
        int4   mB = __ldcs(&m4[i + TPB]);

        bool a0 = mA.x > 0, a1 = mA.y > 0, a2 = mA.z > 0, a3 = mA.w > 0;
        bool b0 = mB.x > 0, b1 = mB.y > 0, b2 = mB.z > 0, b3 = mB.w > 0;
        if (a0) { sn += 1.f; sp += pA.x; sg += gA.x; spp += pA.x*pA.x; spg += pA.x*gA.x; }
        if (a1) { sn += 1.f; sp += pA.y; sg += gA.y; spp += pA.y*pA.y; spg += pA.y*gA.y; }
        if (a2) { sn += 1.f; sp += pA.z; sg += gA.z; spp += pA.z*pA.z; spg += pA.z*gA.z; }
        if (a3) { sn += 1.f; sp += pA.w; sg += gA.w; spp += pA.w*pA.w; spg += pA.w*gA.w; }
        if (b0) { sn += 1.f; sp += pB.x; sg += gB.x; spp += pB.x*pB.x; spg += pB.x*gB.x; }
        if (b1) { sn += 1.f; sp += pB.y; sg += gB.y; spp += pB.y*pB.y; spg += pB.y*gB.y; }
        if (b2) { sn += 1.f; sp += pB.z; sg += gB.z; spp += pB.z*pB.z; spg += pB.z*gB.z; }
        if (b3) { sn += 1.f; sp += pB.w; sg += gB.w; spp += pB.w*pB.w; spg += pB.w*gB.w; }

        unsigned balA0 = __ballot_sync(FULLM, a0);
        unsigned balA1 = __ballot_sync(FULLM, a1);
        unsigned balA2 = __ballot_sync(FULLM, a2);
        unsigned balA3 = __ballot_sync(FULLM, a3);
        unsigned balB0 = __ballot_sync(FULLM, b0);
        unsigned balB1 = __ballot_sync(FULLM, b1);
        unsigned balB2 = __ballot_sync(FULLM, b2);
        unsigned balB3 = __ballot_sync(FULLM, b3);
        int o0 = __popc(balA0);
        int o1 = o0 + __popc(balA1);
        int o2 = o1 + __popc(balA2);
        int o3 = o2 + __popc(balA3);
        int o4 = o3 + __popc(balB0);
        int o5 = o4 + __popc(balB1);
        int o6 = o5 + __popc(balB2);
        int tot = o6 + __popc(balB3);
        int base = 0;
        if (lane == 0 && tot) base = atomicAdd(&s_cnt, tot);
        base = __shfl_sync(FULLM, base, 0);
        if (a0) out[base      + __popc(balA0 & lmask)] = make_float2(pA.x, gA.x);
        if (a1) out[base + o0 + __popc(balA1 & lmask)] = make_float2(pA.y, gA.y);
        if (a2) out[base + o1 + __popc(balA2 & lmask)] = make_float2(pA.z, gA.z);
        if (a3) out[base + o2 + __popc(balA3 & lmask)] = make_float2(pA.w, gA.w);
        if (b0) out[base + o3 + __popc(balB0 & lmask)] = make_float2(pB.x, gB.x);
        if (b1) out[base + o4 + __popc(balB1 & lmask)] = make_float2(pB.y, gB.y);
        if (b2) out[base + o5 + __popc(balB2 & lmask)] = make_float2(pB.z, gB.z);
        if (b3) out[base + o6 + __popc(balB3 & lmask)] = make_float2(pB.w, gB.w);
    }
    // remainder (at most one iteration per thread)
    for (; i < end; i += TPB) {
        float4 p = __ldcs(&p4[i]);
        float4 g = __ldcs(&g4[i]);
        int4   m = __ldcs(&m4[i]);
        bool v0 = m.x > 0, v1 = m.y > 0, v2 = m.z > 0, v3 = m.w > 0;
        if (v0) { sn += 1.f; sp += p.x; sg += g.x; spp += p.x*p.x; spg += p.x*g.x; }
        if (v1) { sn += 1.f; sp += p.y; sg += g.y; spp += p.y*p.y; spg += p.y*g.y; }
        if (v2) { sn += 1.f; sp += p.z; sg += g.z; spp += p.z*p.z; spg += p.z*g.z; }
        if (v3) { sn += 1.f; sp += p.w; sg += g.w; spp += p.w*p.w; spg += p.w*g.w; }
        unsigned bal0 = __ballot_sync(FULLM, v0);
        unsigned bal1 = __ballot_sync(FULLM, v1);
        unsigned bal2 = __ballot_sync(FULLM, v2);
        unsigned bal3 = __ballot_sync(FULLM, v3);
        int c0   = __popc(bal0);
        int c01  = c0  + __popc(bal1);
        int c012 = c01 + __popc(bal2);
        int tot  = c012 + __popc(bal3);
        int base = 0;
        if (lane == 0 && tot) base = atomicAdd(&s_cnt, tot);
        base = __shfl_sync(FULLM, base, 0);
        if (v0) out[base        + __popc(bal0 & lmask)] = make_float2(p.x, g.x);
        if (v1) out[base + c0   + __popc(bal1 & lmask)] = make_float2(p.y, g.y);
        if (v2) out[base + c01  + __popc(bal2 & lmask)] = make_float2(p.z, g.z);
        if (v3) out[base + c012 + __popc(bal3 & lmask)] = make_float2(p.w, g.w);
    }

    sn = warp_sum(sn); sp = warp_sum(sp); sg = warp_sum(sg);
    spp = warp_sum(spp); spg = warp_sum(spg);
    __shared__ float ws[5][8];
    int w = threadIdx.x >> 5;
    if (lane == 0) { ws[0][w]=sn; ws[1][w]=sp; ws[2][w]=sg; ws[3][w]=spp; ws[4][w]=spg; }
    __syncthreads();
    if (w == 0) {
        float a0 = lane < 8 ? ws[0][lane] : 0.f;
        float a1 = lane < 8 ? ws[1][lane] : 0.f;
        float a2 = lane < 8 ? ws[2][lane] : 0.f;
        float a3 = lane < 8 ? ws[3][lane] : 0.f;
        float a4 = lane < 8 ? ws[4][lane] : 0.f;
        a0 = warp_sum(a0); a1 = warp_sum(a1); a2 = warp_sum(a2);
        a3 = warp_sum(a3); a4 = warp_sum(a4);
        if (lane == 0) {
            g_part[b][blockIdx.x][0] = a0;
            g_part[b][blockIdx.x][1] = a1;
            g_part[b][blockIdx.x][2] = a2;
            g_part[b][blockIdx.x][3] = a3;
            g_part[b][blockIdx.x][4] = a4;
            g_segcnt[b][blockIdx.x] = s_cnt;
        }
    }
}

// ------------------------------ 2. finalize --------------------------------
__global__ void finalize_kernel(float* __restrict__ out0) {
    int b = blockIdx.x;
    int tid = threadIdx.x;
    for (int i = tid; i < 2048; i += blockDim.x) g_hcnt[b][i] = 0u;
    if (tid == 0) {
        g_candcnt[b] = 0;
        g_sumbelow[b] = 0.0;
        if (b == 0) *out0 = 0.f;
    }
    if (tid < 32) {
        double v0 = (double)g_part[b][tid][0];
        double v1 = (double)g_part[b][tid][1];
        double v2 = (double)g_part[b][tid][2];
        double v3 = (double)g_part[b][tid][3];
        double v4 = (double)g_part[b][tid][4];
        v0 = warp_sum_d(v0); v1 = warp_sum_d(v1); v2 = warp_sum_d(v2);
        v3 = warp_sum_d(v3); v4 = warp_sum_d(v4);
        if (tid == 0) {
            double n  = v0;
            double ns = n < 1.0 ? 1.0 : n;
            double md = v1 / ns, mz = v2 / ns;
            double var = v3 / ns - md * md;
            double cov = v4 / ns - md * mz;
            double alpha = cov / (var + 1e-6);
            double beta  = mz - alpha * md;
            g_alpha[b] = (float)alpha;
            g_beta[b]  = (float)beta;
            int k = (int)floorf(0.8f * (float)n);   // reference-matching f32 arith
            g_k[b] = k;
            g_rank[b] = (long long)k - 1;
        }
    }
}

// ------------------------------ 3. hist ------------------------------------
__global__ __launch_bounds__(TPB) void hist_kernel() {
    int b = blockIdx.y;
    __shared__ unsigned int sh[2048];
    for (int i = threadIdx.x; i < 2048; i += TPB) sh[i] = 0u;
    __syncthreads();

    int cnt = g_segcnt[b][blockIdx.x];
    const float2* in = g_pair + (size_t)b * NMAX + (size_t)blockIdx.x * SEGLEN;
    float a = g_alpha[b], be = g_beta[b];

    int i = threadIdx.x;
    for (; i + 3*TPB < cnt; i += 4*TPB) {
        float2 q0 = in[i];
        float2 q1 = in[i + TPB];
        float2 q2 = in[i + 2*TPB];
        float2 q3 = in[i + 3*TPB];
        float r0 = fabsf(fmaf(a, q0.x, be) - q0.y);
        float r1 = fabsf(fmaf(a, q1.x, be) - q1.y);
        float r2 = fabsf(fmaf(a, q2.x, be) - q2.y);
        float r3 = fabsf(fmaf(a, q3.x, be) - q3.y);
        atomicAdd(&sh[__float_as_uint(r0) >> 21], 1u);
        atomicAdd(&sh[__float_as_uint(r1) >> 21], 1u);
        atomicAdd(&sh[__float_as_uint(r2) >> 21], 1u);
        atomicAdd(&sh[__float_as_uint(r3) >> 21], 1u);
    }
    for (; i < cnt; i += TPB) {
        float2 pg = in[i];
        float r = fabsf(fmaf(a, pg.x, be) - pg.y);
        atomicAdd(&sh[__float_as_uint(r) >> 21], 1u);
    }
    __syncthreads();
    for (int j = threadIdx.x; j < 2048; j += TPB) {
        unsigned c = sh[j];
        if (c) atomicAdd(&g_hcnt[b][j], c);
    }
}

// ---------------------- 4. compact (+level-0 select) -----------------------
__global__ __launch_bounds__(TPB) void compact_kernel() {
    int b = blockIdx.y;
    int tid = threadIdx.x;
    int lane = tid & 31, w = tid >> 5;

    __shared__ unsigned int s_buf[CAP];
    __shared__ int wtot[8];
    __shared__ int s_bin;
    __shared__ long long s_before, s_rankin;
    __shared__ int s_local, s_gbase;

    if (tid == 0) { s_bin = -1; s_local = 0; }
    long long r = g_rank[b];      // k-1; finalize-owned
    __syncthreads();

    // level-0 selection scan over 2048 bins (identical in every block; L2-hot)
    unsigned int c[8];
    int mysum = 0;
    #pragma unroll
    for (int j = 0; j < 8; j++) { c[j] = g_hcnt[b][tid*8+j]; mysum += (int)c[j]; }
    int incl = warp_scan_incl(mysum, lane);
    if (lane == 31) wtot[w] = incl;
    __syncthreads();
    int wbase = 0;
    #pragma unroll
    for (int j = 0; j < 8; j++) wbase += (j < w) ? wtot[j] : 0;
    long long base = (long long)wbase + incl - mysum;
    if (r >= 0 && r >= base && r < base + mysum) {
        long long cum = base;
        #pragma unroll
        for (int j = 0; j < 8; j++) {
            if (r < cum + (long long)c[j]) {
                s_bin = tid*8+j; s_before = cum; s_rankin = r - cum; break;
            }
            cum += (long long)c[j];
        }
    }
    __syncthreads();

    int sel = s_bin;
    if (sel < 0) {                        // k == 0 case
        if (tid == 0 && blockIdx.x == 0) g_sel0[b] = -1;
        return;
    }
    unsigned selu = (unsigned)sel;
    if (tid == 0 && blockIdx.x == 0) {
        g_sel0[b] = sel;
        g_rank2[b] = s_rankin;
        g_cntbelow[b] = s_before;   // exact from scan
    }

    int cnt = g_segcnt[b][blockIdx.x];
    const float2* in = g_pair + (size_t)b * NMAX + (size_t)blockIdx.x * SEGLEN;
    unsigned int* cand = g_cand + (size_t)b * NMAX;
    float a = g_alpha[b], be = g_beta[b];

    float sbelow = 0.f;
    // single sweep in tiles; ILP-4 loads inside each tile; flush on watermark
    for (int t0 = 0; t0 < cnt; t0 += TILE) {
        int tend = t0 + TILE < cnt ? t0 + TILE : cnt;
        int i = t0 + tid;
        for (; i + 3*TPB < tend; i += 4*TPB) {
            float2 q0 = in[i];
            float2 q1 = in[i + TPB];
            float2 q2 = in[i + 2*TPB];
            float2 q3 = in[i + 3*TPB];
            float r0 = fabsf(fmaf(a, q0.x, be) - q0.y);
            float r1 = fabsf(fmaf(a, q1.x, be) - q1.y);
            float r2 = fabsf(fmaf(a, q2.x, be) - q2.y);
            float r3 = fabsf(fmaf(a, q3.x, be) - q3.y);
            unsigned b0 = __float_as_uint(r0), t0b = b0 >> 21;
            unsigned b1 = __float_as_uint(r1), t1b = b1 >> 21;
            unsigned b2 = __float_as_uint(r2), t2b = b2 >> 21;
            unsigned b3 = __float_as_uint(r3), t3b = b3 >> 21;
            if (t0b < selu) sbelow += r0;
            else if (t0b == selu) s_buf[atomicAdd(&s_local, 1)] = b0;
            if (t1b < selu) sbelow += r1;
            else if (t1b == selu) s_buf[atomicAdd(&s_local, 1)] = b1;
            if (t2b < selu) sbelow += r2;
            else if (t2b == selu) s_buf[atomicAdd(&s_local, 1)] = b2;
            if (t3b < selu) sbelow += r3;
            else if (t3b == selu) s_buf[atomicAdd(&s_local, 1)] = b3;
        }
        for (; i < tend; i += TPB) {
            float2 pg = in[i];
            float rr = fabsf(fmaf(a, pg.x, be) - pg.y);
            unsigned bits = __float_as_uint(rr);
            unsigned top = bits >> 21;
            if (top < selu) sbelow += rr;
            else if (top == selu) s_buf[atomicAdd(&s_local, 1)] = bits;
        }
        // flush if next tile could overflow
        if (t0 + TILE < cnt) {
            __syncthreads();
            int nloc = s_local;
            if (nloc + TILE > CAP) {
                if (tid == 0) {
                    s_gbase = atomicAdd(&g_candcnt[b], nloc);
                    s_local = 0;
                }
                __syncthreads();
                int gb = s_gbase;
                for (int j = tid; j < nloc; j += TPB) cand[gb + j] = s_buf[j];
                __syncthreads();
            }
        }
    }
    // final flush
    __syncthreads();
    {
        int nloc = s_local;
        if (nloc > 0) {
            if (tid == 0) s_gbase = atomicAdd(&g_candcnt[b], nloc);
            __syncthreads();
            int gb = s_gbase;
            for (int j = tid; j < nloc; j += TPB) cand[gb + j] = s_buf[j];
        }
    }

    // block-reduce below-bin sum
    float sb = warp_sum(sbelow);
    __shared__ float wsum[8];
    if (lane == 0) wsum[w] = sb;
    __syncthreads();
    if (tid == 0) {
        float tot = 0.f;
        #pragma unroll
        for (int j = 0; j < 8; j++) tot += wsum[j];
        if (tot != 0.f) atomicAdd(&g_sumbelow[b], (double)tot);
    }
}

// ------------------------------ 5. finish ----------------------------------
#define FTPB 1024
__global__ __launch_bounds__(FTPB) void finish_kernel(float* __restrict__ out0) {
    int b = blockIdx.x;
    int tid = threadIdx.x;
    int lane = tid & 31, w = tid >> 5;
    int sel0 = g_sel0[b];
    int k = g_k[b];

    __shared__ unsigned int hist[2048];
    __shared__ int wtot[32];
    __shared__ int s_bin;
    __shared__ long long s_before;
    __shared__ double sred[32];
    __shared__ long long lred[32];

    if (sel0 < 0 || k <= 0) return;   // contributes 0 to the mean

    int m = g_candcnt[b];
    long long rw = g_rank2[b];
    const unsigned int* cand = g_cand + (size_t)b * NMAX;

    // ---- pass A: bits[20:10], 2048 bins (4x unrolled loads for MLP) ----
    for (int i = tid; i < 2048; i += FTPB) hist[i] = 0u;
    __syncthreads();
    {
        int i = tid;
        for (; i + 3*FTPB < m; i += 4*FTPB) {
            unsigned b0 = cand[i];
            unsigned b1 = cand[i + FTPB];
            unsigned b2 = cand[i + 2*FTPB];
            unsigned b3 = cand[i + 3*FTPB];
            atomicAdd(&hist[(b0 >> 10) & 2047u], 1u);
            atomicAdd(&hist[(b1 >> 10) & 2047u], 1u);
            atomicAdd(&hist[(b2 >> 10) & 2047u], 1u);
            atomicAdd(&hist[(b3 >> 10) & 2047u], 1u);
        }
        for (; i < m; i += FTPB)
            atomicAdd(&hist[(cand[i] >> 10) & 2047u], 1u);
    }
    __syncthreads();
    {
        int c0 = (int)hist[tid*2], c1 = (int)hist[tid*2+1];
        int mysum = c0 + c1;
        int incl = warp_scan_incl(mysum, lane);
        if (lane == 31) wtot[w] = incl;
        __syncthreads();
        int wbase = 0;
        for (int j = 0; j < w; j++) wbase += wtot[j];
        long long base = (long long)wbase + incl - mysum;
        if (rw >= base && rw < base + mysum) {
            if (rw < base + c0) { s_bin = tid*2;   s_before = base; }
            else                { s_bin = tid*2+1; s_before = base + c0; }
        }
        __syncthreads();
    }
    int selA = s_bin;
    rw -= s_before;
    __syncthreads();

    // ---- pass B: bits[9:0], 1024 bins (4x unrolled) ----
    for (int i = tid; i < 1024; i += FTPB) hist[i] = 0u;
    __syncthreads();
    {
        unsigned selAu = (unsigned)selA;
        int i = tid;
        for (; i + 3*FTPB < m; i += 4*FTPB) {
            unsigned b0 = cand[i];
            unsigned b1 = cand[i + FTPB];
            unsigned b2 = cand[i + 2*FTPB];
            unsigned b3 = cand[i + 3*FTPB];
            if (((b0 >> 10) & 2047u) == selAu) atomicAdd(&hist[b0 & 1023u], 1u);
            if (((b1 >> 10) & 2047u) == selAu) atomicAdd(&hist[b1 & 1023u], 1u);
            if (((b2 >> 10) & 2047u) == selAu) atomicAdd(&hist[b2 & 1023u], 1u);
            if (((b3 >> 10) & 2047u) == selAu) atomicAdd(&hist[b3 & 1023u], 1u);
        }
        for (; i < m; i += FTPB) {
            unsigned bits = cand[i];
            if (((bits >> 10) & 2047u) == selAu)
                atomicAdd(&hist[bits & 1023u], 1u);
        }
    }
    __syncthreads();
    {
        int mysum = (int)hist[tid & 1023];
        int incl = warp_scan_incl(mysum, lane);
        if (lane == 31) wtot[w] = incl;
        __syncthreads();
        int wbase = 0;
        for (int j = 0; j < w; j++) wbase += wtot[j];
        long long base = (long long)wbase + incl - mysum;
        if (rw >= base && rw < base + mysum) s_bin = tid;
        __syncthreads();
    }
    int selB = s_bin;
    unsigned v_bits = ((unsigned)sel0 << 21) | ((unsigned)selA << 10) | (unsigned)selB;
    float v = __uint_as_float(v_bits);

    // ---- pass C: sum/count of candidates strictly below v (4x unrolled) ----
    double s = 0.0;
    long long c = 0;
    {
        int i = tid;
        for (; i + 3*FTPB < m; i += 4*FTPB) {
            unsigned b0 = cand[i];
            unsigned b1 = cand[i + FTPB];
            unsigned b2 = cand[i + 2*FTPB];
            unsigned b3 = cand[i + 3*FTPB];
            if (b0 < v_bits) { s += (double)__uint_as_float(b0); c++; }
            if (b1 < v_bits) { s += (double)__uint_as_float(b1); c++; }
            if (b2 < v_bits) { s += (double)__uint_as_float(b2); c++; }
            if (b3 < v_bits) { s += (double)__uint_as_float(b3); c++; }
        }
        for (; i < m; i += FTPB) {
            unsigned bits = cand[i];
            if (bits < v_bits) { s += (double)__uint_as_float(bits); c++; }
        }
    }
    s = warp_sum_d(s);
    c = warp_sum_ll(c);
    if (lane == 0) { sred[w] = s; lred[w] = c; }
    __syncthreads();
    if (w == 0) {
        double sv = sred[lane];
        long long cv = lred[lane];
        sv = warp_sum_d(sv);
        cv = warp_sum_ll(cv);
        if (lane == 0) {
            long long total_less = g_cntbelow[b] + cv;
            double kept = g_sumbelow[b] + sv +
                          (double)((long long)k - total_less) * (double)v;
            float loss = (float)(kept / (double)k);
            atomicAdd(out0, loss / (float)BB);
        }
    }
}

// ------------------------------ launch -------------------------------------
extern "C" void kernel_launch(void* const* d_in, const int* in_sizes, int n_in,
                              void* d_out, int out_size) {
    const float* pred = (const float*)d_in[0];
    const float* gt   = (const float*)d_in[1];
    const int*   mask = (const int*)d_in[2];
    float* out = (float*)d_out;

    int total = in_sizes[0];
    int N = total / BB;

    dim3 grid(BLKX, BB);

    pack_kernel<<<grid, TPB>>>(pred, gt, mask, N);
    finalize_kernel<<<BB, TPB>>>(out);
    hist_kernel<<<grid, TPB>>>();
    compact_kernel<<<grid, TPB>>>();
    finish_kernel<<<BB, FTPB>>>(out);
}